// round 1
// baseline (speedup 1.0000x reference)
#include <cuda_runtime.h>
#include <math.h>

#define NB 8
#define CI 256
#define CM 192
#define CO 128
#define LV 512
#define HH 128
#define WW 128
#define OH 256
#define OW 256
#define ICB 8
#define OCB 64

// Scratch + precomputed tensors (static device globals; no allocs).
__device__ float g_h[(size_t)NB * CM * OH * OW];       // upconv output h [8,192,256,256]
__device__ float g_wT_up[CI * 9 * CM];                 // [cin][tap][cout]
__device__ float g_wT_cv[CM * 9 * CO];                 // [cin][tap][cout]
__device__ float g_s_up[NB * CI];
__device__ float g_s_cv[NB * CM];
__device__ float g_s_rgb[NB * CO];
__device__ float g_isg_up[NB * CM];
__device__ float g_isg_cv[NB * CO];

// ---------------------------------------------------------------------------
// Weight transpose: w_up [i][o][t] -> g_wT_up [i][t][o];
//                   w_conv [o][i][t] -> g_wT_cv [i][t][o]
// ---------------------------------------------------------------------------
__global__ void k_transpose(const float* __restrict__ w_up,
                            const float* __restrict__ w_conv) {
    int idx = blockIdx.x * 256 + threadIdx.x;
    const int tot_up = CI * CM * 9;
    if (idx < tot_up) {
        int t = idx % 9;
        int o = (idx / 9) % CM;
        int i = idx / (9 * CM);
        g_wT_up[(i * 9 + t) * CM + o] = w_up[idx];
    }
    const int tot_cv = CO * CM * 9;
    if (idx < tot_cv) {
        int t = idx % 9;
        int i = (idx / 9) % CM;
        int o = idx / (9 * CM);
        g_wT_cv[(i * 9 + t) * CO + o] = w_conv[idx];
    }
}

// ---------------------------------------------------------------------------
// Styles: s[n][c] = v[n] . sw[c] + sb[c] + 1
// which: 0 -> g_s_up (C=256), 1 -> g_s_cv (C=192), 2 -> g_s_rgb (C=128)
// ---------------------------------------------------------------------------
__global__ void k_style(const float* __restrict__ v, const float* __restrict__ sw,
                        const float* __restrict__ sb, int C, int which) {
    int c = blockIdx.x * 128 + threadIdx.x;
    int n = blockIdx.y;
    if (c >= C) return;
    const float* vp = v + n * LV;
    const float* wp = sw + c * LV;
    float acc = 0.f;
#pragma unroll 8
    for (int l = 0; l < LV; l++) acc = fmaf(vp[l], wp[l], acc);
    float r = acc + sb[c] + 1.0f;
    if (which == 0) g_s_up[n * C + c] = r;
    else if (which == 1) g_s_cv[n * C + c] = r;
    else g_s_rgb[n * C + c] = r;
}

// ---------------------------------------------------------------------------
// Demodulation: isg[n][o] = 1/sqrt(sum_i s[n][i]^2 * sum_t w[i][o][t]^2 + eps)
// which: 0 -> up (IC=256, OC=192), 1 -> conv (IC=192, OC=128)
// ---------------------------------------------------------------------------
__global__ void k_sigma(int which) {
    int OC = which ? CO : CM;
    int IC = which ? CM : CI;
    const float* wT = which ? g_wT_cv : g_wT_up;
    const float* s = which ? g_s_cv : g_s_up;
    int o = blockIdx.x * 128 + threadIdx.x;
    int n = blockIdx.y;
    if (o >= OC) return;
    float acc = 0.f;
    for (int i = 0; i < IC; i++) {
        float wsq = 0.f;
        const float* wp = wT + (i * 9) * OC + o;
#pragma unroll
        for (int t = 0; t < 9; t++) { float w = wp[t * OC]; wsq = fmaf(w, w, wsq); }
        float sv = s[n * IC + i];
        acc = fmaf(sv * sv, wsq, acc);
    }
    float inv = 1.0f / sqrtf(acc + 1e-8f);
    if (which) g_isg_cv[n * OC + o] = inv;
    else g_isg_up[n * OC + o] = inv;
}

// ---------------------------------------------------------------------------
// Upconv (modulated transposed conv k=3 s=2 p=1 op=1), parity-decomposed.
// Output tile 16x16 per block; 4 parity classes, each 8x8 half-res m-grid.
// Block z = n*3 + ob (ob selects 64 of 192 output channels).
// Thread: ocg = tid&7 (oc = ob*64 + ocg + 8j), pxg = tid>>3,
//   cls = pxg>>3 (warp-uniform), my = pxg&7, 8 px at mx = 0..7.
// ---------------------------------------------------------------------------
__global__ __launch_bounds__(256) void k_upconv(
    const float* __restrict__ x, const float* __restrict__ noise1,
    const float* __restrict__ b_up, const float* __restrict__ ns1p) {
    __shared__ float sX[ICB][9][9];
    __shared__ float sW[ICB][9][OCB];

    int n = blockIdx.z / 3, ob = blockIdx.z % 3;
    int m0y = blockIdx.y * 8, m0x = blockIdx.x * 8;
    int tid = threadIdx.x;
    int ocg = tid & 7;
    int pxg = tid >> 3;
    int cls = pxg >> 3;        // same class across a warp
    int my = pxg & 7;
    int dy = cls >> 1, dx = cls & 1;

    // Tap tables. Output (oy,ox) = (2(m0y+my)+dy, 2(m0x+mx)+dx).
    //  dy=0: tap ky=1, iy=my.           dy=1: ky=0 -> iy=my+1; ky=2 -> iy=my.
    //  dx likewise for kx.
    int nt;
    int xoff[4], woff[4];
    if (cls == 0) {            // (even,even): w[1][1]
        nt = 1;
        xoff[0] = my * 9;           woff[0] = 4 * OCB + ocg;
    } else if (cls == 1) {     // (even,odd): w[1][0]@ix=mx+1, w[1][2]@ix=mx
        nt = 2;
        xoff[0] = my * 9 + 1;       woff[0] = 3 * OCB + ocg;
        xoff[1] = my * 9;           woff[1] = 5 * OCB + ocg;
    } else if (cls == 2) {     // (odd,even): w[0][1]@iy=my+1, w[2][1]@iy=my
        nt = 2;
        xoff[0] = (my + 1) * 9;     woff[0] = 1 * OCB + ocg;
        xoff[1] = my * 9;           woff[1] = 7 * OCB + ocg;
    } else {                   // (odd,odd): 4 corner taps
        nt = 4;
        xoff[0] = (my + 1) * 9 + 1; woff[0] = 0 * OCB + ocg;
        xoff[1] = (my + 1) * 9;     woff[1] = 2 * OCB + ocg;
        xoff[2] = my * 9 + 1;       woff[2] = 6 * OCB + ocg;
        xoff[3] = my * 9;           woff[3] = 8 * OCB + ocg;
    }

    float acc[8][8];
#pragma unroll
    for (int j = 0; j < 8; j++)
#pragma unroll
        for (int p = 0; p < 8; p++) acc[j][p] = 0.f;

    for (int ic0 = 0; ic0 < CI; ic0 += ICB) {
        // Load input tile (style-modulated), 9x9 per channel; clamp-to-zero OOB.
        for (int e = tid; e < ICB * 81; e += 256) {
            int ic = e / 81;
            int rr = (e % 81) / 9;
            int cc = e % 9;
            int gy = m0y + rr, gx = m0x + cc;
            float vv = 0.f;
            if (gy < HH && gx < WW)
                vv = x[((n * CI + ic0 + ic) * HH + gy) * WW + gx] *
                     g_s_up[n * CI + ic0 + ic];
            sX[ic][rr][cc] = vv;
        }
        // Load weight chunk (coalesced 64-wide rows).
        for (int e = tid; e < ICB * 9 * OCB; e += 256) {
            int ol = e & 63;
            int t = (e >> 6) % 9;
            int ic = e / (9 * OCB);
            sW[ic][t][ol] = g_wT_up[((ic0 + ic) * 9 + t) * CM + ob * OCB + ol];
        }
        __syncthreads();

        for (int ic = 0; ic < ICB; ic++) {
            const float* xb = &sX[ic][0][0];
            const float* wb = &sW[ic][0][0];
            for (int tt = 0; tt < nt; tt++) {
                const float* xr = xb + xoff[tt];
                const float* wr = wb + woff[tt];
                float wv[8], xv[8];
#pragma unroll
                for (int j = 0; j < 8; j++) wv[j] = wr[8 * j];
#pragma unroll
                for (int p = 0; p < 8; p++) xv[p] = xr[p];
#pragma unroll
                for (int j = 0; j < 8; j++)
#pragma unroll
                    for (int p = 0; p < 8; p++)
                        acc[j][p] = fmaf(wv[j], xv[p], acc[j][p]);
            }
        }
        __syncthreads();
    }

    // Epilogue: demod + bias + noise + leaky_relu(0.2), write h.
    float ns1 = *ns1p;
    int oy = 2 * (m0y + my) + dy;
    float nz[8];
#pragma unroll
    for (int p = 0; p < 8; p++) {
        int ox = 2 * (m0x + p) + dx;
        nz[p] = ns1 * noise1[(n * OH + oy) * OW + ox];
    }
#pragma unroll
    for (int j = 0; j < 8; j++) {
        int oc = ob * OCB + ocg + 8 * j;
        float isg = g_isg_up[n * CM + oc];
        float bb = b_up[oc];
        float* hp = &g_h[(((size_t)n * CM + oc) * OH + oy) * OW];
#pragma unroll
        for (int p = 0; p < 8; p++) {
            int ox = 2 * (m0x + p) + dx;
            float val = fmaf(acc[j][p], isg, bb) + nz[p];
            val = val > 0.f ? val : 0.2f * val;
            hp[ox] = val;
        }
    }
}

// ---------------------------------------------------------------------------
// Conv2: modulated 3x3 conv pad 1, h[8,192,256,256] -> h2[8,128,256,256].
// Output tile 16x16; block z = n*2 + ob (ob: 64 of 128 out channels).
// Thread: ocg = tid&7, pxg = tid>>3; my = pxg>>1, mx0 = (pxg&1)*8.
// ---------------------------------------------------------------------------
__global__ __launch_bounds__(256) void k_conv2(
    const float* __restrict__ noise2, const float* __restrict__ b_conv,
    const float* __restrict__ ns2p, float* __restrict__ out) {
    __shared__ float sX[ICB][18][18];
    __shared__ float sW[ICB][9][OCB];

    int n = blockIdx.z >> 1, ob = blockIdx.z & 1;
    int o0y = blockIdx.y * 16, o0x = blockIdx.x * 16;
    int tid = threadIdx.x;
    int ocg = tid & 7;
    int pxg = tid >> 3;
    int my = pxg >> 1;
    int mx0 = (pxg & 1) * 8;

    float acc[8][8];
#pragma unroll
    for (int j = 0; j < 8; j++)
#pragma unroll
        for (int p = 0; p < 8; p++) acc[j][p] = 0.f;

    for (int ic0 = 0; ic0 < CM; ic0 += ICB) {
        // Input tile 18x18 (pad 1), style-modulated.
        for (int e = tid; e < ICB * 324; e += 256) {
            int ic = e / 324;
            int rr = (e % 324) / 18;
            int cc = e % 18;
            int gy = o0y - 1 + rr, gx = o0x - 1 + cc;
            float vv = 0.f;
            if (gy >= 0 && gy < OH && gx >= 0 && gx < OW)
                vv = g_h[(((size_t)n * CM + ic0 + ic) * OH + gy) * OW + gx] *
                     g_s_cv[n * CM + ic0 + ic];
            sX[ic][rr][cc] = vv;
        }
        for (int e = tid; e < ICB * 9 * OCB; e += 256) {
            int ol = e & 63;
            int t = (e >> 6) % 9;
            int ic = e / (9 * OCB);
            sW[ic][t][ol] = g_wT_cv[((ic0 + ic) * 9 + t) * CO + ob * OCB + ol];
        }
        __syncthreads();

        for (int ic = 0; ic < ICB; ic++) {
#pragma unroll
            for (int t = 0; t < 9; t++) {
                int ky = t / 3, kx = t % 3;
                float wv[8], xv[8];
#pragma unroll
                for (int j = 0; j < 8; j++) wv[j] = sW[ic][t][ocg + 8 * j];
#pragma unroll
                for (int p = 0; p < 8; p++) xv[p] = sX[ic][my + ky][mx0 + p + kx];
#pragma unroll
                for (int j = 0; j < 8; j++)
#pragma unroll
                    for (int p = 0; p < 8; p++)
                        acc[j][p] = fmaf(wv[j], xv[p], acc[j][p]);
            }
        }
        __syncthreads();
    }

    float ns2 = *ns2p;
    int oy = o0y + my;
    float nz[8];
#pragma unroll
    for (int p = 0; p < 8; p++) {
        int ox = o0x + mx0 + p;
        nz[p] = ns2 * noise2[(n * OH + oy) * OW + ox];
    }
#pragma unroll
    for (int j = 0; j < 8; j++) {
        int oc = ob * OCB + ocg + 8 * j;
        float isg = g_isg_cv[n * CO + oc];
        float bb = b_conv[oc];
        float* op = &out[(((size_t)n * CO + oc) * OH + oy) * OW];
#pragma unroll
        for (int p = 0; p < 8; p++) {
            float val = fmaf(acc[j][p], isg, bb) + nz[p];
            val = val > 0.f ? val : 0.2f * val;
            op[o0x + mx0 + p] = val;
        }
    }
}

// ---------------------------------------------------------------------------
// to-RGB (modulated 1x1, no demod) + leaky + bilinear-upsampled skip.
// grid (1, 256, 8), block 256: one thread per output pixel column.
// ---------------------------------------------------------------------------
__global__ void k_rgb(const float* __restrict__ y, const float* __restrict__ w_rgb,
                      const float* __restrict__ b_rgb, const float* __restrict__ h2,
                      float* __restrict__ yout) {
    __shared__ float cf[3][CO];
    int n = blockIdx.z;
    int oy = blockIdx.y;
    int ox = threadIdx.x;
    int tid = threadIdx.x;
    if (tid < CO) {
        float s = g_s_rgb[n * CO + tid];
#pragma unroll
        for (int c = 0; c < 3; c++) cf[c][tid] = w_rgb[c * CO + tid] * s;
    }
    __syncthreads();

    float a0 = b_rgb[0], a1 = b_rgb[1], a2 = b_rgb[2];
    const float* hp = h2 + (((size_t)n * CO) * OH + oy) * OW + ox;
#pragma unroll 4
    for (int o = 0; o < CO; o++) {
        float hv = hp[(size_t)o * OH * OW];
        a0 = fmaf(hv, cf[0][o], a0);
        a1 = fmaf(hv, cf[1][o], a1);
        a2 = fmaf(hv, cf[2][o], a2);
    }
    a0 = a0 > 0.f ? a0 : 0.2f * a0;
    a1 = a1 > 0.f ? a1 : 0.2f * a1;
    a2 = a2 > 0.f ? a2 : 0.2f * a2;
    float rr[3] = {a0, a1, a2};

    // Bilinear upsample, half-pixel centers, edge clamp.
    float fy = 0.5f * oy - 0.25f;
    int iyf = (int)floorf(fy);
    float wy = fy - (float)iyf;
    int iy0 = iyf < 0 ? 0 : iyf;
    int iy1 = (iyf + 1) > (HH - 1) ? (HH - 1) : (iyf + 1);
    float fx = 0.5f * ox - 0.25f;
    int ixf = (int)floorf(fx);
    float wx = fx - (float)ixf;
    int ix0 = ixf < 0 ? 0 : ixf;
    int ix1 = (ixf + 1) > (WW - 1) ? (WW - 1) : (ixf + 1);

#pragma unroll
    for (int c = 0; c < 3; c++) {
        const float* yp = y + ((size_t)(n * 3 + c) * HH) * WW;
        float v00 = yp[iy0 * WW + ix0], v01 = yp[iy0 * WW + ix1];
        float v10 = yp[iy1 * WW + ix0], v11 = yp[iy1 * WW + ix1];
        float vt = v00 + (v01 - v00) * wx;
        float vb = v10 + (v11 - v10) * wx;
        float val = vt + (vb - vt) * wy;
        yout[(((size_t)n * 3 + c) * OH + oy) * OW + ox] = val + rr[c];
    }
}

// ---------------------------------------------------------------------------
extern "C" void kernel_launch(void* const* d_in, const int* in_sizes, int n_in,
                              void* d_out, int out_size) {
    const float* x       = (const float*)d_in[0];
    const float* v       = (const float*)d_in[1];
    const float* y       = (const float*)d_in[2];
    const float* noise1  = (const float*)d_in[3];
    const float* noise2  = (const float*)d_in[4];
    const float* w_up    = (const float*)d_in[5];
    const float* b_up    = (const float*)d_in[6];
    const float* sw_up   = (const float*)d_in[7];
    const float* sb_up   = (const float*)d_in[8];
    const float* w_conv  = (const float*)d_in[9];
    const float* b_conv  = (const float*)d_in[10];
    const float* sw_conv = (const float*)d_in[11];
    const float* sb_conv = (const float*)d_in[12];
    const float* w_rgb   = (const float*)d_in[13];
    const float* b_rgb   = (const float*)d_in[14];
    const float* sw_rgb  = (const float*)d_in[15];
    const float* sb_rgb  = (const float*)d_in[16];
    const float* ns1     = (const float*)d_in[17];
    const float* ns2     = (const float*)d_in[18];
    float* out = (float*)d_out;

    (void)sb_up; (void)sb_conv; (void)sb_rgb; (void)in_sizes; (void)n_in; (void)out_size;

    k_transpose<<<1728, 256>>>(w_up, w_conv);

    dim3 gs2(2, NB), gs1(1, NB);
    k_style<<<gs2, 128>>>(v, sw_up, sb_up, CI, 0);
    k_style<<<gs2, 128>>>(v, sw_conv, sb_conv, CM, 1);
    k_style<<<gs1, 128>>>(v, sw_rgb, sb_rgb, CO, 2);

    k_sigma<<<gs2, 128>>>(0);
    k_sigma<<<gs1, 128>>>(1);

    dim3 gup(16, 16, NB * 3);
    k_upconv<<<gup, 256>>>(x, noise1, b_up, ns1);

    dim3 gcv(16, 16, NB * 2);
    k_conv2<<<gcv, 256>>>(noise2, b_conv, ns2, out);

    dim3 grgb(1, 256, NB);
    k_rgb<<<grgb, 256>>>(y, w_rgb, b_rgb, out, out + (size_t)NB * CO * OH * OW);
}

// round 2
// speedup vs baseline: 1.2696x; 1.2696x over previous
#include <cuda_runtime.h>
#include <math.h>

#define NB 8
#define CI 256
#define CM 192
#define CO 128
#define LV 512
#define HH 128
#define WW 128
#define OH 256
#define OW 256
#define ICB 8
#define OCB 64

typedef unsigned long long u64t;

__device__ __forceinline__ u64t dup2(float a) {
    u64t r; asm("mov.b64 %0, {%1, %1};" : "=l"(r) : "f"(a)); return r;
}
__device__ __forceinline__ void fma2(u64t& d, u64t a, u64t b) {
    asm("fma.rn.f32x2 %0, %1, %2, %0;" : "+l"(d) : "l"(a), "l"(b));
}
__device__ __forceinline__ void unpack2(u64t d, float& lo, float& hi) {
    asm("mov.b64 {%0, %1}, %2;" : "=f"(lo), "=f"(hi) : "l"(d));
}

// Scratch + precomputed tensors (static device globals; no allocs).
__device__ float g_h[(size_t)NB * CM * OH * OW];       // upconv output h [8,192,256,256]
__device__ float g_wT_up[CI * 9 * CM];                 // [cin][tap][cout]
__device__ float g_wT_cv[CM * 9 * CO];                 // [cin][tap][cout]
__device__ float g_wsq_up[CM * CI];                    // [o][i] sum_t w^2
__device__ float g_wsq_cv[CO * CM];
__device__ float g_s_up[NB * CI];
__device__ float g_s_cv[NB * CM];
__device__ float g_s_rgb[NB * CO];
__device__ float g_isg_up[NB * CM];
__device__ float g_isg_cv[NB * CO];

// ---------------------------------------------------------------------------
// Weight transpose + per-(o,i) squared-weight sums.
// ---------------------------------------------------------------------------
__global__ void k_transpose(const float* __restrict__ w_up,
                            const float* __restrict__ w_conv) {
    int idx = blockIdx.x * 256 + threadIdx.x;
    const int tot_up = CI * CM * 9;
    if (idx < tot_up) {
        int t = idx % 9;
        int o = (idx / 9) % CM;
        int i = idx / (9 * CM);
        float w = w_up[idx];
        g_wT_up[(i * 9 + t) * CM + o] = w;
        if (t == 0) {
            float acc = 0.f;
            const float* p = w_up + (i * CM + o) * 9;
#pragma unroll
            for (int tt = 0; tt < 9; tt++) acc = fmaf(p[tt], p[tt], acc);
            g_wsq_up[o * CI + i] = acc;
        }
    }
    const int tot_cv = CO * CM * 9;
    if (idx < tot_cv) {
        int t = idx % 9;
        int i = (idx / 9) % CM;
        int o = idx / (9 * CM);
        g_wT_cv[(i * 9 + t) * CO + o] = w_conv[idx];
        if (t == 0) {
            float acc = 0.f;
            const float* p = w_conv + (o * CM + i) * 9;
#pragma unroll
            for (int tt = 0; tt < 9; tt++) acc = fmaf(p[tt], p[tt], acc);
            g_wsq_cv[o * CM + i] = acc;
        }
    }
}

// ---------------------------------------------------------------------------
// Styles: warp-per-channel dot product, coalesced + shfl reduce.
// grid (C/8, N), block 256.
// ---------------------------------------------------------------------------
__global__ void k_style(const float* __restrict__ v, const float* __restrict__ sw,
                        const float* __restrict__ sb, int C, int which) {
    int warp = threadIdx.x >> 5, lane = threadIdx.x & 31;
    int c = blockIdx.x * 8 + warp;
    int n = blockIdx.y;
    if (c >= C) return;
    const float* vp = v + n * LV;
    const float* wp = sw + c * LV;
    float acc = 0.f;
#pragma unroll
    for (int l = lane; l < LV; l += 32) acc = fmaf(vp[l], wp[l], acc);
#pragma unroll
    for (int s = 16; s > 0; s >>= 1) acc += __shfl_xor_sync(0xFFFFFFFF, acc, s);
    if (lane == 0) {
        float r = acc + sb[c] + 1.0f;
        if (which == 0) g_s_up[n * C + c] = r;
        else if (which == 1) g_s_cv[n * C + c] = r;
        else g_s_rgb[n * C + c] = r;
    }
}

// ---------------------------------------------------------------------------
// Demodulation: warp-per-(n,o), coalesced over i.
// grid (OC/4, N), block 128.
// ---------------------------------------------------------------------------
__global__ void k_sigma(int which) {
    int OC = which ? CO : CM;
    int IC = which ? CM : CI;
    const float* wsq = which ? g_wsq_cv : g_wsq_up;
    const float* s = which ? g_s_cv : g_s_up;
    int warp = threadIdx.x >> 5, lane = threadIdx.x & 31;
    int o = blockIdx.x * 4 + warp;
    int n = blockIdx.y;
    float acc = 0.f;
    for (int i = lane; i < IC; i += 32) {
        float sv = s[n * IC + i];
        acc = fmaf(sv * sv, wsq[o * IC + i], acc);
    }
#pragma unroll
    for (int sh = 16; sh > 0; sh >>= 1) acc += __shfl_xor_sync(0xFFFFFFFF, acc, sh);
    if (lane == 0) {
        float inv = 1.0f / sqrtf(acc + 1e-8f);
        if (which) g_isg_cv[n * OC + o] = inv;
        else g_isg_up[n * OC + o] = inv;
    }
}

// ---------------------------------------------------------------------------
// Upconv (modulated transposed conv k=3 s=2 p=1 op=1), parity-decomposed,
// f32x2 packed FMA pairing along output channels.
// Output tile 16x16; 4 parity classes, each 8x8 half-res m-grid.
// Class -> warp map balanced across SMSPs: cls = wid<4 ? wid : 7-wid.
// Thread: oc = ob*64 + ocg*8 + j (j=0..7 contiguous -> LDS.64 weight pairs).
// ---------------------------------------------------------------------------
__global__ __launch_bounds__(256, 2) void k_upconv(
    const float* __restrict__ x, const float* __restrict__ noise1,
    const float* __restrict__ b_up, const float* __restrict__ ns1p) {
    __shared__ __align__(16) float sX[ICB][9][9];
    __shared__ __align__(16) float sW[ICB][9][OCB];

    int n = blockIdx.z / 3, ob = blockIdx.z % 3;
    int m0y = blockIdx.y * 8, m0x = blockIdx.x * 8;
    int tid = threadIdx.x;
    int wid = tid >> 5, ln = tid & 31;
    int cls = (wid < 4) ? wid : (7 - wid);   // SMSP-balanced: pairs (1,4),(2,2)
    int hh = (wid < 4) ? 0 : 1;
    int idx = hh * 32 + ln;                  // 0..63 within class
    int ocg = idx & 7;
    int my = idx >> 3;                       // 0..7
    int dy = cls >> 1, dx = cls & 1;

    // Tap tables. Output (oy,ox) = (2(m0y+my)+dy, 2(m0x+mx)+dx).
    int nt;
    int xoff[4], woff[4];
    if (cls == 0) {            // (even,even): w[1][1]
        nt = 1;
        xoff[0] = my * 9;           woff[0] = 4 * OCB;
    } else if (cls == 1) {     // (even,odd): w[1][0]@ix=mx+1, w[1][2]@ix=mx
        nt = 2;
        xoff[0] = my * 9 + 1;       woff[0] = 3 * OCB;
        xoff[1] = my * 9;           woff[1] = 5 * OCB;
    } else if (cls == 2) {     // (odd,even): w[0][1]@iy=my+1, w[2][1]@iy=my
        nt = 2;
        xoff[0] = (my + 1) * 9;     woff[0] = 1 * OCB;
        xoff[1] = my * 9;           woff[1] = 7 * OCB;
    } else {                   // (odd,odd): 4 corner taps
        nt = 4;
        xoff[0] = (my + 1) * 9 + 1; woff[0] = 0 * OCB;
        xoff[1] = (my + 1) * 9;     woff[1] = 2 * OCB;
        xoff[2] = my * 9 + 1;       woff[2] = 6 * OCB;
        xoff[3] = my * 9;           woff[3] = 8 * OCB;
    }

    u64t acc2[4][8];
#pragma unroll
    for (int jp = 0; jp < 4; jp++)
#pragma unroll
        for (int p = 0; p < 8; p++) acc2[jp][p] = 0ULL;

    for (int ic0 = 0; ic0 < CI; ic0 += ICB) {
        for (int e = tid; e < ICB * 81; e += 256) {
            int ic = e / 81;
            int rr = (e % 81) / 9;
            int cc = e % 9;
            int gy = m0y + rr, gx = m0x + cc;
            float vv = 0.f;
            if (gy < HH && gx < WW)
                vv = x[((n * CI + ic0 + ic) * HH + gy) * WW + gx] *
                     g_s_up[n * CI + ic0 + ic];
            sX[ic][rr][cc] = vv;
        }
        for (int e = tid; e < ICB * 9 * OCB; e += 256) {
            int ol = e & 63;
            int t = (e >> 6) % 9;
            int ic = e / (9 * OCB);
            sW[ic][t][ol] = g_wT_up[((ic0 + ic) * 9 + t) * CM + ob * OCB + ol];
        }
        __syncthreads();

        for (int ic = 0; ic < ICB; ic++) {
            const float* xb = &sX[ic][0][0];
            const float* wb = &sW[ic][0][0];
            for (int tt = 0; tt < nt; tt++) {
                const float* xr = xb + xoff[tt];
                const u64t* wr = (const u64t*)(wb + woff[tt] + ocg * 8);
                u64t w0 = wr[0], w1 = wr[1], w2 = wr[2], w3 = wr[3];
#pragma unroll
                for (int p = 0; p < 8; p++) {
                    u64t xd = dup2(xr[p]);
                    fma2(acc2[0][p], w0, xd);
                    fma2(acc2[1][p], w1, xd);
                    fma2(acc2[2][p], w2, xd);
                    fma2(acc2[3][p], w3, xd);
                }
            }
        }
        __syncthreads();
    }

    // Epilogue: demod + bias + noise + leaky_relu(0.2), write h.
    float ns1 = *ns1p;
    int oy = 2 * (m0y + my) + dy;
    float nz[8];
#pragma unroll
    for (int p = 0; p < 8; p++) {
        int ox = 2 * (m0x + p) + dx;
        nz[p] = ns1 * noise1[(n * OH + oy) * OW + ox];
    }
#pragma unroll
    for (int jp = 0; jp < 4; jp++) {
#pragma unroll
        for (int half = 0; half < 2; half++) {
            int oc = ob * OCB + ocg * 8 + 2 * jp + half;
            float isg = g_isg_up[n * CM + oc];
            float bb = b_up[oc];
            float* hp = &g_h[(((size_t)n * CM + oc) * OH + oy) * OW];
#pragma unroll
            for (int p = 0; p < 8; p++) {
                float lo, hi;
                unpack2(acc2[jp][p], lo, hi);
                float a = half ? hi : lo;
                int ox = 2 * (m0x + p) + dx;
                float val = fmaf(a, isg, bb) + nz[p];
                val = val > 0.f ? val : 0.2f * val;
                hp[ox] = val;
            }
        }
    }
}

// ---------------------------------------------------------------------------
// Conv2: modulated 3x3 conv pad 1, h[8,192,256,256] -> h2[8,128,256,256].
// f32x2 packed, oc pairs contiguous.
// ---------------------------------------------------------------------------
__global__ __launch_bounds__(256, 2) void k_conv2(
    const float* __restrict__ noise2, const float* __restrict__ b_conv,
    const float* __restrict__ ns2p, float* __restrict__ out) {
    __shared__ __align__(16) float sX[ICB][18][18];
    __shared__ __align__(16) float sW[ICB][9][OCB];

    int n = blockIdx.z >> 1, ob = blockIdx.z & 1;
    int o0y = blockIdx.y * 16, o0x = blockIdx.x * 16;
    int tid = threadIdx.x;
    int ocg = tid & 7;
    int pxg = tid >> 3;
    int my = pxg >> 1;
    int mx0 = (pxg & 1) * 8;

    u64t acc2[4][8];
#pragma unroll
    for (int jp = 0; jp < 4; jp++)
#pragma unroll
        for (int p = 0; p < 8; p++) acc2[jp][p] = 0ULL;

    for (int ic0 = 0; ic0 < CM; ic0 += ICB) {
        for (int e = tid; e < ICB * 324; e += 256) {
            int ic = e / 324;
            int rr = (e % 324) / 18;
            int cc = e % 18;
            int gy = o0y - 1 + rr, gx = o0x - 1 + cc;
            float vv = 0.f;
            if (gy >= 0 && gy < OH && gx >= 0 && gx < OW)
                vv = g_h[(((size_t)n * CM + ic0 + ic) * OH + gy) * OW + gx] *
                     g_s_cv[n * CM + ic0 + ic];
            sX[ic][rr][cc] = vv;
        }
        for (int e = tid; e < ICB * 9 * OCB; e += 256) {
            int ol = e & 63;
            int t = (e >> 6) % 9;
            int ic = e / (9 * OCB);
            sW[ic][t][ol] = g_wT_cv[((ic0 + ic) * 9 + t) * CO + ob * OCB + ol];
        }
        __syncthreads();

        for (int ic = 0; ic < ICB; ic++) {
#pragma unroll
            for (int t = 0; t < 9; t++) {
                int ky = t / 3, kx = t % 3;
                const u64t* wr = (const u64t*)(&sW[ic][t][ocg * 8]);
                u64t w0 = wr[0], w1 = wr[1], w2 = wr[2], w3 = wr[3];
                const float* xr = &sX[ic][my + ky][mx0 + kx];
#pragma unroll
                for (int p = 0; p < 8; p++) {
                    u64t xd = dup2(xr[p]);
                    fma2(acc2[0][p], w0, xd);
                    fma2(acc2[1][p], w1, xd);
                    fma2(acc2[2][p], w2, xd);
                    fma2(acc2[3][p], w3, xd);
                }
            }
        }
        __syncthreads();
    }

    float ns2 = *ns2p;
    int oy = o0y + my;
    float nz[8];
#pragma unroll
    for (int p = 0; p < 8; p++) {
        int ox = o0x + mx0 + p;
        nz[p] = ns2 * noise2[(n * OH + oy) * OW + ox];
    }
#pragma unroll
    for (int jp = 0; jp < 4; jp++) {
#pragma unroll
        for (int half = 0; half < 2; half++) {
            int oc = ob * OCB + ocg * 8 + 2 * jp + half;
            float isg = g_isg_cv[n * CO + oc];
            float bb = b_conv[oc];
            float* op = &out[(((size_t)n * CO + oc) * OH + oy) * OW];
#pragma unroll
            for (int p = 0; p < 8; p++) {
                float lo, hi;
                unpack2(acc2[jp][p], lo, hi);
                float a = half ? hi : lo;
                float val = fmaf(a, isg, bb) + nz[p];
                val = val > 0.f ? val : 0.2f * val;
                op[o0x + mx0 + p] = val;
            }
        }
    }
}

// ---------------------------------------------------------------------------
// to-RGB (modulated 1x1, no demod) + leaky + bilinear-upsampled skip.
// ---------------------------------------------------------------------------
__global__ void k_rgb(const float* __restrict__ y, const float* __restrict__ w_rgb,
                      const float* __restrict__ b_rgb, const float* __restrict__ h2,
                      float* __restrict__ yout) {
    __shared__ float cf[3][CO];
    int n = blockIdx.z;
    int oy = blockIdx.y;
    int ox = threadIdx.x;
    int tid = threadIdx.x;
    if (tid < CO) {
        float s = g_s_rgb[n * CO + tid];
#pragma unroll
        for (int c = 0; c < 3; c++) cf[c][tid] = w_rgb[c * CO + tid] * s;
    }
    __syncthreads();

    float a0 = b_rgb[0], a1 = b_rgb[1], a2 = b_rgb[2];
    const float* hp = h2 + (((size_t)n * CO) * OH + oy) * OW + ox;
#pragma unroll 4
    for (int o = 0; o < CO; o++) {
        float hv = hp[(size_t)o * OH * OW];
        a0 = fmaf(hv, cf[0][o], a0);
        a1 = fmaf(hv, cf[1][o], a1);
        a2 = fmaf(hv, cf[2][o], a2);
    }
    a0 = a0 > 0.f ? a0 : 0.2f * a0;
    a1 = a1 > 0.f ? a1 : 0.2f * a1;
    a2 = a2 > 0.f ? a2 : 0.2f * a2;
    float rr[3] = {a0, a1, a2};

    float fy = 0.5f * oy - 0.25f;
    int iyf = (int)floorf(fy);
    float wy = fy - (float)iyf;
    int iy0 = iyf < 0 ? 0 : iyf;
    int iy1 = (iyf + 1) > (HH - 1) ? (HH - 1) : (iyf + 1);
    float fx = 0.5f * ox - 0.25f;
    int ixf = (int)floorf(fx);
    float wx = fx - (float)ixf;
    int ix0 = ixf < 0 ? 0 : ixf;
    int ix1 = (ixf + 1) > (WW - 1) ? (WW - 1) : (ixf + 1);

#pragma unroll
    for (int c = 0; c < 3; c++) {
        const float* yp = y + ((size_t)(n * 3 + c) * HH) * WW;
        float v00 = yp[iy0 * WW + ix0], v01 = yp[iy0 * WW + ix1];
        float v10 = yp[iy1 * WW + ix0], v11 = yp[iy1 * WW + ix1];
        float vt = v00 + (v01 - v00) * wx;
        float vb = v10 + (v11 - v10) * wx;
        float val = vt + (vb - vt) * wy;
        yout[(((size_t)n * 3 + c) * OH + oy) * OW + ox] = val + rr[c];
    }
}

// ---------------------------------------------------------------------------
extern "C" void kernel_launch(void* const* d_in, const int* in_sizes, int n_in,
                              void* d_out, int out_size) {
    const float* x       = (const float*)d_in[0];
    const float* v       = (const float*)d_in[1];
    const float* y       = (const float*)d_in[2];
    const float* noise1  = (const float*)d_in[3];
    const float* noise2  = (const float*)d_in[4];
    const float* w_up    = (const float*)d_in[5];
    const float* b_up    = (const float*)d_in[6];
    const float* sw_up   = (const float*)d_in[7];
    const float* sb_up   = (const float*)d_in[8];
    const float* w_conv  = (const float*)d_in[9];
    const float* b_conv  = (const float*)d_in[10];
    const float* sw_conv = (const float*)d_in[11];
    const float* sb_conv = (const float*)d_in[12];
    const float* w_rgb   = (const float*)d_in[13];
    const float* b_rgb   = (const float*)d_in[14];
    const float* sw_rgb  = (const float*)d_in[15];
    const float* sb_rgb  = (const float*)d_in[16];
    const float* ns1     = (const float*)d_in[17];
    const float* ns2     = (const float*)d_in[18];
    float* out = (float*)d_out;

    (void)in_sizes; (void)n_in; (void)out_size;

    k_transpose<<<1728, 256>>>(w_up, w_conv);

    dim3 gsu(CI / 8, NB), gsc(CM / 8, NB), gsr(CO / 8, NB);
    k_style<<<gsu, 256>>>(v, sw_up, sb_up, CI, 0);
    k_style<<<gsc, 256>>>(v, sw_conv, sb_conv, CM, 1);
    k_style<<<gsr, 256>>>(v, sw_rgb, sb_rgb, CO, 2);

    dim3 gg0(CM / 4, NB), gg1(CO / 4, NB);
    k_sigma<<<gg0, 128>>>(0);
    k_sigma<<<gg1, 128>>>(1);

    dim3 gup(16, 16, NB * 3);
    k_upconv<<<gup, 256>>>(x, noise1, b_up, ns1);

    dim3 gcv(16, 16, NB * 2);
    k_conv2<<<gcv, 256>>>(noise2, b_conv, ns2, out);

    dim3 grgb(1, 256, NB);
    k_rgb<<<grgb, 256>>>(y, w_rgb, b_rgb, out, out + (size_t)NB * CO * OH * OW);
}

// round 4
// speedup vs baseline: 1.4302x; 1.1265x over previous
#include <cuda_runtime.h>
#include <cuda_bf16.h>
#include <math.h>
#include <cstdint>

#define NB 8
#define CI 256
#define CM 192
#define CO 128
#define LV 512
#define HH 128
#define WW 128
#define OH 256
#define OW 256
#define ICB 8
#define OCB 64

typedef unsigned long long u64t;

// ===================== f32x2 helpers (upconv) ==============================
__device__ __forceinline__ u64t dup2(float a) {
    u64t r; asm("mov.b64 %0, {%1, %1};" : "=l"(r) : "f"(a)); return r;
}
__device__ __forceinline__ void fma2(u64t& d, u64t a, u64t b) {
    asm("fma.rn.f32x2 %0, %1, %2, %0;" : "+l"(d) : "l"(a), "l"(b));
}
__device__ __forceinline__ void unpack2(u64t d, float& lo, float& hi) {
    asm("mov.b64 {%0, %1}, %2;" : "=f"(lo), "=f"(hi) : "l"(d));
}

// ===================== warp-MMA helpers (base ISA, sm_80+) =================
__device__ __forceinline__ uint32_t smem_u32(const void* p) {
    uint32_t a;
    asm("{ .reg .u64 t; cvta.to.shared.u64 t, %1; cvt.u32.u64 %0, t; }"
        : "=r"(a) : "l"(p));
    return a;
}
__device__ __forceinline__ void ldsm_x4(uint32_t* r, uint32_t addr) {
    asm volatile("ldmatrix.sync.aligned.m8n8.x4.shared.b16 {%0,%1,%2,%3}, [%4];"
                 : "=r"(r[0]), "=r"(r[1]), "=r"(r[2]), "=r"(r[3]) : "r"(addr));
}
__device__ __forceinline__ void mma16816(float* d, const uint32_t* a,
                                         uint32_t b0, uint32_t b1) {
    asm volatile(
        "mma.sync.aligned.m16n8k16.row.col.f32.bf16.bf16.f32 "
        "{%0,%1,%2,%3}, {%4,%5,%6,%7}, {%8,%9}, {%0,%1,%2,%3};"
        : "+f"(d[0]), "+f"(d[1]), "+f"(d[2]), "+f"(d[3])
        : "r"(a[0]), "r"(a[1]), "r"(a[2]), "r"(a[3]), "r"(b0), "r"(b1));
}

// bf16 2-term split: pack (hi | lo<<16)
__device__ __forceinline__ uint32_t splitpack(float v) {
    __nv_bfloat16 h = __float2bfloat16(v);
    float hf = __bfloat162float(h);
    __nv_bfloat16 l = __float2bfloat16(v - hf);
    __nv_bfloat16_raw hr = *(__nv_bfloat16_raw*)&h;
    __nv_bfloat16_raw lr = *(__nv_bfloat16_raw*)&l;
    return (uint32_t)hr.x | ((uint32_t)lr.x << 16);
}

// ===================== device globals ======================================
__device__ float g_h[(size_t)NB * CM * OH * OW];     // upconv output
__device__ float g_wT_up[CI * 9 * CM];               // [cin][tap][cout]
__device__ uint32_t g_wb_cv[9 * CO * CM];            // [tap][oc][ic] split-packed bf16
__device__ float g_wsq_up[CM * CI];
__device__ float g_wsq_cv[CO * CM];
__device__ float g_s_up[NB * CI];
__device__ float g_s_cv[NB * CM];
__device__ float g_s_rgb[NB * CO];
__device__ float g_isg_up[NB * CM];
__device__ float g_isg_cv[NB * CO];

// ---------------------------------------------------------------------------
// Weight prep: transpose for upconv, split-pack for conv2, squared sums.
// ---------------------------------------------------------------------------
__global__ void k_transpose(const float* __restrict__ w_up,
                            const float* __restrict__ w_conv) {
    int idx = blockIdx.x * 256 + threadIdx.x;
    const int tot_up = CI * CM * 9;
    if (idx < tot_up) {
        int t = idx % 9;
        int o = (idx / 9) % CM;
        int i = idx / (9 * CM);
        float w = w_up[idx];
        g_wT_up[(i * 9 + t) * CM + o] = w;
        if (t == 0) {
            float acc = 0.f;
            const float* p = w_up + (i * CM + o) * 9;
#pragma unroll
            for (int tt = 0; tt < 9; tt++) acc = fmaf(p[tt], p[tt], acc);
            g_wsq_up[o * CI + i] = acc;
        }
    }
    const int tot_cv = CO * CM * 9;
    if (idx < tot_cv) {
        int t = idx % 9;
        int i = (idx / 9) % CM;
        int o = idx / (9 * CM);
        float w = w_conv[idx];
        g_wb_cv[(t * CO + o) * CM + i] = splitpack(w);
        if (t == 0) {
            float acc = 0.f;
            const float* p = w_conv + (o * CM + i) * 9;
#pragma unroll
            for (int tt = 0; tt < 9; tt++) acc = fmaf(p[tt], p[tt], acc);
            g_wsq_cv[o * CM + i] = acc;
        }
    }
}

// ---------------------------------------------------------------------------
__global__ void k_style(const float* __restrict__ v, const float* __restrict__ sw,
                        const float* __restrict__ sb, int C, int which) {
    int warp = threadIdx.x >> 5, lane = threadIdx.x & 31;
    int c = blockIdx.x * 8 + warp;
    int n = blockIdx.y;
    if (c >= C) return;
    const float* vp = v + n * LV;
    const float* wp = sw + c * LV;
    float acc = 0.f;
#pragma unroll
    for (int l = lane; l < LV; l += 32) acc = fmaf(vp[l], wp[l], acc);
#pragma unroll
    for (int s = 16; s > 0; s >>= 1) acc += __shfl_xor_sync(0xFFFFFFFF, acc, s);
    if (lane == 0) {
        float r = acc + sb[c] + 1.0f;
        if (which == 0) g_s_up[n * C + c] = r;
        else if (which == 1) g_s_cv[n * C + c] = r;
        else g_s_rgb[n * C + c] = r;
    }
}

// ---------------------------------------------------------------------------
__global__ void k_sigma(int which) {
    int OC = which ? CO : CM;
    int IC = which ? CM : CI;
    const float* wsq = which ? g_wsq_cv : g_wsq_up;
    const float* s = which ? g_s_cv : g_s_up;
    int warp = threadIdx.x >> 5, lane = threadIdx.x & 31;
    int o = blockIdx.x * 4 + warp;
    int n = blockIdx.y;
    float acc = 0.f;
    for (int i = lane; i < IC; i += 32) {
        float sv = s[n * IC + i];
        acc = fmaf(sv * sv, wsq[o * IC + i], acc);
    }
#pragma unroll
    for (int sh = 16; sh > 0; sh >>= 1) acc += __shfl_xor_sync(0xFFFFFFFF, acc, sh);
    if (lane == 0) {
        float inv = 1.0f / sqrtf(acc + 1e-8f);
        if (which) g_isg_cv[n * OC + o] = inv;
        else g_isg_up[n * OC + o] = inv;
    }
}

// ---------------------------------------------------------------------------
// Upconv: f32x2 parity-decomposed (Round 2, unchanged).
// ---------------------------------------------------------------------------
__global__ __launch_bounds__(256, 2) void k_upconv(
    const float* __restrict__ x, const float* __restrict__ noise1,
    const float* __restrict__ b_up, const float* __restrict__ ns1p) {
    __shared__ __align__(16) float sX[ICB][9][9];
    __shared__ __align__(16) float sW[ICB][9][OCB];

    int n = blockIdx.z / 3, ob = blockIdx.z % 3;
    int m0y = blockIdx.y * 8, m0x = blockIdx.x * 8;
    int tid = threadIdx.x;
    int wid = tid >> 5, ln = tid & 31;
    int cls = (wid < 4) ? wid : (7 - wid);
    int hh = (wid < 4) ? 0 : 1;
    int idx = hh * 32 + ln;
    int ocg = idx & 7;
    int my = idx >> 3;
    int dy = cls >> 1, dx = cls & 1;

    int nt;
    int xoff[4], woff[4];
    if (cls == 0) {
        nt = 1;
        xoff[0] = my * 9;           woff[0] = 4 * OCB;
    } else if (cls == 1) {
        nt = 2;
        xoff[0] = my * 9 + 1;       woff[0] = 3 * OCB;
        xoff[1] = my * 9;           woff[1] = 5 * OCB;
    } else if (cls == 2) {
        nt = 2;
        xoff[0] = (my + 1) * 9;     woff[0] = 1 * OCB;
        xoff[1] = my * 9;           woff[1] = 7 * OCB;
    } else {
        nt = 4;
        xoff[0] = (my + 1) * 9 + 1; woff[0] = 0 * OCB;
        xoff[1] = (my + 1) * 9;     woff[1] = 2 * OCB;
        xoff[2] = my * 9 + 1;       woff[2] = 6 * OCB;
        xoff[3] = my * 9;           woff[3] = 8 * OCB;
    }

    u64t acc2[4][8];
#pragma unroll
    for (int jp = 0; jp < 4; jp++)
#pragma unroll
        for (int p = 0; p < 8; p++) acc2[jp][p] = 0ULL;

    for (int ic0 = 0; ic0 < CI; ic0 += ICB) {
        for (int e = tid; e < ICB * 81; e += 256) {
            int ic = e / 81;
            int rr = (e % 81) / 9;
            int cc = e % 9;
            int gy = m0y + rr, gx = m0x + cc;
            float vv = 0.f;
            if (gy < HH && gx < WW)
                vv = x[((n * CI + ic0 + ic) * HH + gy) * WW + gx] *
                     g_s_up[n * CI + ic0 + ic];
            sX[ic][rr][cc] = vv;
        }
        for (int e = tid; e < ICB * 9 * OCB; e += 256) {
            int ol = e & 63;
            int t = (e >> 6) % 9;
            int ic = e / (9 * OCB);
            sW[ic][t][ol] = g_wT_up[((ic0 + ic) * 9 + t) * CM + ob * OCB + ol];
        }
        __syncthreads();

        for (int ic = 0; ic < ICB; ic++) {
            const float* xb = &sX[ic][0][0];
            const float* wb = &sW[ic][0][0];
            for (int tt = 0; tt < nt; tt++) {
                const float* xr = xb + xoff[tt];
                const u64t* wr = (const u64t*)(wb + woff[tt] + ocg * 8);
                u64t w0 = wr[0], w1 = wr[1], w2 = wr[2], w3 = wr[3];
#pragma unroll
                for (int p = 0; p < 8; p++) {
                    u64t xd = dup2(xr[p]);
                    fma2(acc2[0][p], w0, xd);
                    fma2(acc2[1][p], w1, xd);
                    fma2(acc2[2][p], w2, xd);
                    fma2(acc2[3][p], w3, xd);
                }
            }
        }
        __syncthreads();
    }

    float ns1 = *ns1p;
    int oy = 2 * (m0y + my) + dy;
    float nz[8];
#pragma unroll
    for (int p = 0; p < 8; p++) {
        int ox = 2 * (m0x + p) + dx;
        nz[p] = ns1 * noise1[(n * OH + oy) * OW + ox];
    }
#pragma unroll
    for (int jp = 0; jp < 4; jp++) {
#pragma unroll
        for (int half_ = 0; half_ < 2; half_++) {
            int oc = ob * OCB + ocg * 8 + 2 * jp + half_;
            float isg = g_isg_up[n * CM + oc];
            float bb = b_up[oc];
            float* hp = &g_h[(((size_t)n * CM + oc) * OH + oy) * OW];
#pragma unroll
            for (int p = 0; p < 8; p++) {
                float lo, hi;
                unpack2(acc2[jp][p], lo, hi);
                float a = half_ ? hi : lo;
                int ox = 2 * (m0x + p) + dx;
                float val = fmaf(a, isg, bb) + nz[p];
                val = val > 0.f ? val : 0.2f * val;
                hp[ox] = val;
            }
        }
    }
}

// ---------------------------------------------------------------------------
// Conv2 via mma.sync (bf16 3-term split): implicit GEMM.
// M = 128 px (8y x 16x), N = 128 oc, K = 9 taps x 6 ic-chunks x 96 k'.
// 8 warps: warp grid 4(M) x 2(N); warp tile 32m x 64n = 2 x 8 m16n8k16 tiles.
// ---------------------------------------------------------------------------
#define APITCH 104                 // bf16 units; 13 x 16B -> LDSM conflict-free
#define RAWP 34
#define SM_A 0
#define SM_B (128 * APITCH * 2)                  // 26624
#define SM_RAW (SM_B + 128 * APITCH * 2)         // 53248
#define SMEM_DYN (SM_RAW + 180 * RAWP * 4)       // 77728
#define EPIP 133                   // f32 pitch for epilogue tile

__global__ __launch_bounds__(256) void k_conv2_mma(
    const float* __restrict__ noise2, const float* __restrict__ b_conv,
    const float* __restrict__ ns2p, float* __restrict__ out) {
    extern __shared__ __align__(16) char smem[];
    uint32_t sA = smem_u32(smem) + SM_A;
    uint32_t sB = smem_u32(smem) + SM_B;
    uint32_t* raw = (uint32_t*)(smem + SM_RAW);
    char* smA = smem + SM_A;
    char* smB = smem + SM_B;

    int tid = threadIdx.x;
    int wid = tid >> 5, lane = tid & 31;
    int wm = wid & 3, wn = wid >> 2;
    int n = blockIdx.z;
    int y0 = blockIdx.y * 8, x0 = blockIdx.x * 16;

    // staging role
    int mrow = tid >> 1;          // 0..127 (row of A and B)
    int hf = tid & 1;             // splits 16 ic-pairs
    int smy = mrow >> 4, smx = mrow & 15;

    // ldmatrix addressing
    int rowsel = lane & 15;
    int ksel = lane >> 4;

    float acc[2][8][4];
#pragma unroll
    for (int mi = 0; mi < 2; mi++)
#pragma unroll
        for (int ni = 0; ni < 8; ni++)
#pragma unroll
            for (int q = 0; q < 4; q++) acc[mi][ni][q] = 0.f;

    for (int c = 0; c < 6; c++) {
        int ic0 = c * 32;
        __syncthreads();
        // ---- load raw halo chunk [180 px][32 ic], style-mod, split-packed
        for (int e = tid; e < 5760; e += 256) {
            int pix = e % 180;
            int k = e / 180;
            int ry = pix / 18, rx = pix % 18;
            int gy = y0 - 1 + ry, gx = x0 - 1 + rx;
            float vv = 0.f;
            if (gy >= 0 && gy < OH && gx >= 0 && gx < OW)
                vv = g_h[(((size_t)n * CM + ic0 + k) * OH + gy) * OW + gx] *
                     g_s_cv[n * CM + ic0 + k];
            raw[pix * RAWP + k] = splitpack(vv);
        }
        __syncthreads();

        for (int t = 0; t < 9; t++) {
            int ky = t / 3, kx = t % 3;
            // ---- stage A [m][k'=region*32+ic] and B [oc][k']
            int pix = (ky + smy) * 18 + (kx + smx);
            const u64t* rp = (const u64t*)(raw + pix * RAWP + hf * 16);
            const u64t* wp = (const u64t*)(g_wb_cv + ((size_t)t * CO + mrow) * CM +
                                           ic0 + hf * 16);
            uint32_t* arow = (uint32_t*)(smA + (mrow * APITCH + hf * 16) * 2);
            uint32_t* brow = (uint32_t*)(smB + (mrow * APITCH + hf * 16) * 2);
#pragma unroll
            for (int q = 0; q < 8; q++) {
                u64t va = rp[q];
                uint32_t a0 = (uint32_t)va, a1 = (uint32_t)(va >> 32);
                uint32_t ahi = __byte_perm(a0, a1, 0x5410);
                uint32_t alo = __byte_perm(a0, a1, 0x7632);
                arow[q] = ahi;                 // region 0: a_hi
                arow[16 + q] = alo;            // region 1: a_lo
                arow[32 + q] = ahi;            // region 2: a_hi
                u64t vb = wp[q];
                uint32_t b0 = (uint32_t)vb, b1 = (uint32_t)(vb >> 32);
                uint32_t bhi = __byte_perm(b0, b1, 0x5410);
                uint32_t blo = __byte_perm(b0, b1, 0x7632);
                brow[q] = bhi;                 // region 0: b_hi
                brow[16 + q] = bhi;            // region 1: b_hi
                brow[32 + q] = blo;            // region 2: b_lo
            }
            __syncthreads();

            // ---- mma phase: 6 k16 steps over k' = 96
#pragma unroll
            for (int kk = 0; kk < 6; kk++) {
                int k0 = kk * 16;
                uint32_t ar[2][4];
#pragma unroll
                for (int mi = 0; mi < 2; mi++)
                    ldsm_x4(ar[mi], sA + ((wm * 32 + mi * 16 + rowsel) * APITCH +
                                          k0 + ksel * 8) * 2);
                uint32_t br[4][4];
#pragma unroll
                for (int nj = 0; nj < 4; nj++)
                    ldsm_x4(br[nj], sB + ((wn * 64 + nj * 16 + rowsel) * APITCH +
                                          k0 + ksel * 8) * 2);
#pragma unroll
                for (int mi = 0; mi < 2; mi++)
#pragma unroll
                    for (int ni = 0; ni < 8; ni++) {
                        int nj = ni >> 1, pr = ni & 1;
                        mma16816(acc[mi][ni], ar[mi], br[nj][pr], br[nj][pr + 2]);
                    }
            }
            __syncthreads();
        }
    }

    // ---- epilogue: acc -> smem [128 px][128 oc] f32, then coalesced store
    float* smf = (float*)smem;
#pragma unroll
    for (int mi = 0; mi < 2; mi++)
#pragma unroll
        for (int ni = 0; ni < 8; ni++) {
            int m = wm * 32 + mi * 16 + (lane >> 2);
            int col = wn * 64 + ni * 8 + (lane & 3) * 2;
            smf[m * EPIP + col] = acc[mi][ni][0];
            smf[m * EPIP + col + 1] = acc[mi][ni][1];
            smf[(m + 8) * EPIP + col] = acc[mi][ni][2];
            smf[(m + 8) * EPIP + col + 1] = acc[mi][ni][3];
        }
    __syncthreads();

    {
        int px = tid & 127;
        int ocl = tid >> 7;
        int my = px >> 4, mx = px & 15;
        int yy = y0 + my, xx = x0 + mx;
        float nz = (*ns2p) * noise2[(n * OH + yy) * OW + xx];
        const float* isgp = g_isg_cv + n * CO;
#pragma unroll 4
        for (int ob = 0; ob < 64; ob++) {
            int oc = ob * 2 + ocl;
            float d = smf[px * EPIP + oc];
            float val = fmaf(d, isgp[oc], b_conv[oc]) + nz;
            val = val > 0.f ? val : 0.2f * val;
            out[(((size_t)n * CO + oc) * OH + yy) * OW + xx] = val;
        }
    }
}

// ---------------------------------------------------------------------------
// to-RGB + bilinear skip (unchanged).
// ---------------------------------------------------------------------------
__global__ void k_rgb(const float* __restrict__ y, const float* __restrict__ w_rgb,
                      const float* __restrict__ b_rgb, const float* __restrict__ h2,
                      float* __restrict__ yout) {
    __shared__ float cf[3][CO];
    int n = blockIdx.z;
    int oy = blockIdx.y;
    int ox = threadIdx.x;
    int tid = threadIdx.x;
    if (tid < CO) {
        float s = g_s_rgb[n * CO + tid];
#pragma unroll
        for (int c = 0; c < 3; c++) cf[c][tid] = w_rgb[c * CO + tid] * s;
    }
    __syncthreads();

    float a0 = b_rgb[0], a1 = b_rgb[1], a2 = b_rgb[2];
    const float* hp = h2 + (((size_t)n * CO) * OH + oy) * OW + ox;
#pragma unroll 4
    for (int o = 0; o < CO; o++) {
        float hv = hp[(size_t)o * OH * OW];
        a0 = fmaf(hv, cf[0][o], a0);
        a1 = fmaf(hv, cf[1][o], a1);
        a2 = fmaf(hv, cf[2][o], a2);
    }
    a0 = a0 > 0.f ? a0 : 0.2f * a0;
    a1 = a1 > 0.f ? a1 : 0.2f * a1;
    a2 = a2 > 0.f ? a2 : 0.2f * a2;
    float rr[3] = {a0, a1, a2};

    float fy = 0.5f * oy - 0.25f;
    int iyf = (int)floorf(fy);
    float wy = fy - (float)iyf;
    int iy0 = iyf < 0 ? 0 : iyf;
    int iy1 = (iyf + 1) > (HH - 1) ? (HH - 1) : (iyf + 1);
    float fx = 0.5f * ox - 0.25f;
    int ixf = (int)floorf(fx);
    float wx = fx - (float)ixf;
    int ix0 = ixf < 0 ? 0 : ixf;
    int ix1 = (ixf + 1) > (WW - 1) ? (WW - 1) : (ixf + 1);

#pragma unroll
    for (int c = 0; c < 3; c++) {
        const float* yp = y + ((size_t)(n * 3 + c) * HH) * WW;
        float v00 = yp[iy0 * WW + ix0], v01 = yp[iy0 * WW + ix1];
        float v10 = yp[iy1 * WW + ix0], v11 = yp[iy1 * WW + ix1];
        float vt = v00 + (v01 - v00) * wx;
        float vb = v10 + (v11 - v10) * wx;
        float val = vt + (vb - vt) * wy;
        yout[(((size_t)n * 3 + c) * OH + oy) * OW + ox] = val + rr[c];
    }
}

// ---------------------------------------------------------------------------
extern "C" void kernel_launch(void* const* d_in, const int* in_sizes, int n_in,
                              void* d_out, int out_size) {
    const float* x       = (const float*)d_in[0];
    const float* v       = (const float*)d_in[1];
    const float* y       = (const float*)d_in[2];
    const float* noise1  = (const float*)d_in[3];
    const float* noise2  = (const float*)d_in[4];
    const float* w_up    = (const float*)d_in[5];
    const float* b_up    = (const float*)d_in[6];
    const float* sw_up   = (const float*)d_in[7];
    const float* sb_up   = (const float*)d_in[8];
    const float* w_conv  = (const float*)d_in[9];
    const float* b_conv  = (const float*)d_in[10];
    const float* sw_conv = (const float*)d_in[11];
    const float* sb_conv = (const float*)d_in[12];
    const float* w_rgb   = (const float*)d_in[13];
    const float* b_rgb   = (const float*)d_in[14];
    const float* sw_rgb  = (const float*)d_in[15];
    const float* sb_rgb  = (const float*)d_in[16];
    const float* ns1     = (const float*)d_in[17];
    const float* ns2     = (const float*)d_in[18];
    float* out = (float*)d_out;

    (void)in_sizes; (void)n_in; (void)out_size;

    k_transpose<<<1728, 256>>>(w_up, w_conv);

    dim3 gsu(CI / 8, NB), gsc(CM / 8, NB), gsr(CO / 8, NB);
    k_style<<<gsu, 256>>>(v, sw_up, sb_up, CI, 0);
    k_style<<<gsc, 256>>>(v, sw_conv, sb_conv, CM, 1);
    k_style<<<gsr, 256>>>(v, sw_rgb, sb_rgb, CO, 2);

    dim3 gg0(CM / 4, NB), gg1(CO / 4, NB);
    k_sigma<<<gg0, 128>>>(0);
    k_sigma<<<gg1, 128>>>(1);

    dim3 gup(16, 16, NB * 3);
    k_upconv<<<gup, 256>>>(x, noise1, b_up, ns1);

    cudaFuncSetAttribute(k_conv2_mma, cudaFuncAttributeMaxDynamicSharedMemorySize,
                         SMEM_DYN);
    dim3 gcv(16, 32, NB);
    k_conv2_mma<<<gcv, 256, SMEM_DYN>>>(noise2, b_conv, ns2, out);

    dim3 grgb(1, 256, NB);
    k_rgb<<<grgb, 256>>>(y, w_rgb, b_rgb, out, out + (size_t)NB * CO * OH * OW);
}

// round 5
// speedup vs baseline: 1.7495x; 1.2232x over previous
#include <cuda_runtime.h>
#include <cuda_bf16.h>
#include <math.h>
#include <cstdint>

#define NB 8
#define CI 256
#define CM 192
#define CO 128
#define LV 512
#define HH 128
#define WW 128
#define OH 256
#define OW 256
#define ICB 8
#define OCB 64

typedef unsigned long long u64t;

// ===================== f32x2 helpers (upconv) ==============================
__device__ __forceinline__ u64t dup2(float a) {
    u64t r; asm("mov.b64 %0, {%1, %1};" : "=l"(r) : "f"(a)); return r;
}
__device__ __forceinline__ void fma2(u64t& d, u64t a, u64t b) {
    asm("fma.rn.f32x2 %0, %1, %2, %0;" : "+l"(d) : "l"(a), "l"(b));
}
__device__ __forceinline__ void unpack2(u64t d, float& lo, float& hi) {
    asm("mov.b64 {%0, %1}, %2;" : "=f"(lo), "=f"(hi) : "l"(d));
}

// ===================== warp-MMA helpers (base ISA, sm_80+) =================
__device__ __forceinline__ uint32_t smem_u32(const void* p) {
    uint32_t a;
    asm("{ .reg .u64 t; cvta.to.shared.u64 t, %1; cvt.u32.u64 %0, t; }"
        : "=r"(a) : "l"(p));
    return a;
}
__device__ __forceinline__ void ldsm_x4(uint32_t* r, uint32_t addr) {
    asm volatile("ldmatrix.sync.aligned.m8n8.x4.shared.b16 {%0,%1,%2,%3}, [%4];"
                 : "=r"(r[0]), "=r"(r[1]), "=r"(r[2]), "=r"(r[3]) : "r"(addr));
}
__device__ __forceinline__ void mma16816(float* d, const uint32_t* a,
                                         uint32_t b0, uint32_t b1) {
    asm volatile(
        "mma.sync.aligned.m16n8k16.row.col.f32.bf16.bf16.f32 "
        "{%0,%1,%2,%3}, {%4,%5,%6,%7}, {%8,%9}, {%0,%1,%2,%3};"
        : "+f"(d[0]), "+f"(d[1]), "+f"(d[2]), "+f"(d[3])
        : "r"(a[0]), "r"(a[1]), "r"(a[2]), "r"(a[3]), "r"(b0), "r"(b1));
}
__device__ __forceinline__ void cpasync16(uint32_t dst, const void* src) {
    asm volatile("cp.async.ca.shared.global [%0], [%1], 16;"
                 :: "r"(dst), "l"(src) : "memory");
}
#define CP_COMMIT() asm volatile("cp.async.commit_group;" ::: "memory")
#define CP_WAIT_ALL() asm volatile("cp.async.wait_group 0;" ::: "memory")

// bf16 2-term split: pack (hi | lo<<16)
__device__ __forceinline__ uint32_t splitpack(float v) {
    __nv_bfloat16 h = __float2bfloat16(v);
    float hf = __bfloat162float(h);
    __nv_bfloat16 l = __float2bfloat16(v - hf);
    __nv_bfloat16_raw hr = *(__nv_bfloat16_raw*)&h;
    __nv_bfloat16_raw lr = *(__nv_bfloat16_raw*)&l;
    return (uint32_t)hr.x | ((uint32_t)lr.x << 16);
}

// ===================== device globals ======================================
__device__ float g_h[(size_t)NB * CM * OH * OW];     // upconv output
__device__ float g_wT_up[CI * 9 * CM];               // [cin][tap][cout]
__device__ __align__(16) __nv_bfloat16 g_wbs[6 * 9 * CO * 96]; // pre-split conv2 B
__device__ float g_wsq_up[CM * CI];
__device__ float g_wsq_cv[CO * CM];
__device__ float g_s_up[NB * CI];
__device__ float g_s_cv[NB * CM];
__device__ float g_s_rgb[NB * CO];
__device__ float g_isg_up[NB * CM];
__device__ float g_isg_cv[NB * CO];

// ---------------------------------------------------------------------------
// Upconv weight transpose + squared sums (up + conv).
// ---------------------------------------------------------------------------
__global__ void k_transpose(const float* __restrict__ w_up,
                            const float* __restrict__ w_conv) {
    int idx = blockIdx.x * 256 + threadIdx.x;
    const int tot_up = CI * CM * 9;
    if (idx < tot_up) {
        int t = idx % 9;
        int o = (idx / 9) % CM;
        int i = idx / (9 * CM);
        float w = w_up[idx];
        g_wT_up[(i * 9 + t) * CM + o] = w;
        if (t == 0) {
            float acc = 0.f;
            const float* p = w_up + (i * CM + o) * 9;
#pragma unroll
            for (int tt = 0; tt < 9; tt++) acc = fmaf(p[tt], p[tt], acc);
            g_wsq_up[o * CI + i] = acc;
        }
    }
    if (idx < CO * CM) {
        int i = idx % CM;
        int o = idx / CM;
        float acc = 0.f;
        const float* p = w_conv + (o * CM + i) * 9;
#pragma unroll
        for (int tt = 0; tt < 9; tt++) acc = fmaf(p[tt], p[tt], acc);
        g_wsq_cv[o * CM + i] = acc;
    }
}

// ---------------------------------------------------------------------------
// Conv2 B prep: g_wbs[c][t][oc][k'] bf16, k' regions = (hi, hi, lo).
// ---------------------------------------------------------------------------
__global__ void k_wprep(const float* __restrict__ w_conv) {
    int idx = blockIdx.x * 256 + threadIdx.x;
    if (idx >= 6 * 9 * CO * 96) return;
    int k = idx % 96;
    int oc = (idx / 96) % CO;
    int t = (idx / (96 * CO)) % 9;
    int c = idx / (96 * CO * 9);
    int r = k >> 5;
    int ic = c * 32 + (k & 31);
    float w = w_conv[(oc * CM + ic) * 9 + t];
    __nv_bfloat16 hi = __float2bfloat16(w);
    __nv_bfloat16 val = (r < 2) ? hi : __float2bfloat16(w - __bfloat162float(hi));
    g_wbs[idx] = val;
}

// ---------------------------------------------------------------------------
__global__ void k_style(const float* __restrict__ v, const float* __restrict__ sw,
                        const float* __restrict__ sb, int C, int which) {
    int warp = threadIdx.x >> 5, lane = threadIdx.x & 31;
    int c = blockIdx.x * 8 + warp;
    int n = blockIdx.y;
    if (c >= C) return;
    const float* vp = v + n * LV;
    const float* wp = sw + c * LV;
    float acc = 0.f;
#pragma unroll
    for (int l = lane; l < LV; l += 32) acc = fmaf(vp[l], wp[l], acc);
#pragma unroll
    for (int s = 16; s > 0; s >>= 1) acc += __shfl_xor_sync(0xFFFFFFFF, acc, s);
    if (lane == 0) {
        float r = acc + sb[c] + 1.0f;
        if (which == 0) g_s_up[n * C + c] = r;
        else if (which == 1) g_s_cv[n * C + c] = r;
        else g_s_rgb[n * C + c] = r;
    }
}

// ---------------------------------------------------------------------------
__global__ void k_sigma(int which) {
    int OC = which ? CO : CM;
    int IC = which ? CM : CI;
    const float* wsq = which ? g_wsq_cv : g_wsq_up;
    const float* s = which ? g_s_cv : g_s_up;
    int warp = threadIdx.x >> 5, lane = threadIdx.x & 31;
    int o = blockIdx.x * 4 + warp;
    int n = blockIdx.y;
    float acc = 0.f;
    for (int i = lane; i < IC; i += 32) {
        float sv = s[n * IC + i];
        acc = fmaf(sv * sv, wsq[o * IC + i], acc);
    }
#pragma unroll
    for (int sh = 16; sh > 0; sh >>= 1) acc += __shfl_xor_sync(0xFFFFFFFF, acc, sh);
    if (lane == 0) {
        float inv = 1.0f / sqrtf(acc + 1e-8f);
        if (which) g_isg_cv[n * OC + o] = inv;
        else g_isg_up[n * OC + o] = inv;
    }
}

// ---------------------------------------------------------------------------
// Upconv: f32x2 parity-decomposed (unchanged).
// ---------------------------------------------------------------------------
__global__ __launch_bounds__(256, 2) void k_upconv(
    const float* __restrict__ x, const float* __restrict__ noise1,
    const float* __restrict__ b_up, const float* __restrict__ ns1p) {
    __shared__ __align__(16) float sX[ICB][9][9];
    __shared__ __align__(16) float sW[ICB][9][OCB];

    int n = blockIdx.z / 3, ob = blockIdx.z % 3;
    int m0y = blockIdx.y * 8, m0x = blockIdx.x * 8;
    int tid = threadIdx.x;
    int wid = tid >> 5, ln = tid & 31;
    int cls = (wid < 4) ? wid : (7 - wid);
    int hh = (wid < 4) ? 0 : 1;
    int idx = hh * 32 + ln;
    int ocg = idx & 7;
    int my = idx >> 3;
    int dy = cls >> 1, dx = cls & 1;

    int nt;
    int xoff[4], woff[4];
    if (cls == 0) {
        nt = 1;
        xoff[0] = my * 9;           woff[0] = 4 * OCB;
    } else if (cls == 1) {
        nt = 2;
        xoff[0] = my * 9 + 1;       woff[0] = 3 * OCB;
        xoff[1] = my * 9;           woff[1] = 5 * OCB;
    } else if (cls == 2) {
        nt = 2;
        xoff[0] = (my + 1) * 9;     woff[0] = 1 * OCB;
        xoff[1] = my * 9;           woff[1] = 7 * OCB;
    } else {
        nt = 4;
        xoff[0] = (my + 1) * 9 + 1; woff[0] = 0 * OCB;
        xoff[1] = (my + 1) * 9;     woff[1] = 2 * OCB;
        xoff[2] = my * 9 + 1;       woff[2] = 6 * OCB;
        xoff[3] = my * 9;           woff[3] = 8 * OCB;
    }

    u64t acc2[4][8];
#pragma unroll
    for (int jp = 0; jp < 4; jp++)
#pragma unroll
        for (int p = 0; p < 8; p++) acc2[jp][p] = 0ULL;

    for (int ic0 = 0; ic0 < CI; ic0 += ICB) {
        for (int e = tid; e < ICB * 81; e += 256) {
            int ic = e / 81;
            int rr = (e % 81) / 9;
            int cc = e % 9;
            int gy = m0y + rr, gx = m0x + cc;
            float vv = 0.f;
            if (gy < HH && gx < WW)
                vv = x[((n * CI + ic0 + ic) * HH + gy) * WW + gx] *
                     g_s_up[n * CI + ic0 + ic];
            sX[ic][rr][cc] = vv;
        }
        for (int e = tid; e < ICB * 9 * OCB; e += 256) {
            int ol = e & 63;
            int t = (e >> 6) % 9;
            int ic = e / (9 * OCB);
            sW[ic][t][ol] = g_wT_up[((ic0 + ic) * 9 + t) * CM + ob * OCB + ol];
        }
        __syncthreads();

        for (int ic = 0; ic < ICB; ic++) {
            const float* xb = &sX[ic][0][0];
            const float* wb = &sW[ic][0][0];
            for (int tt = 0; tt < nt; tt++) {
                const float* xr = xb + xoff[tt];
                const u64t* wr = (const u64t*)(wb + woff[tt] + ocg * 8);
                u64t w0 = wr[0], w1 = wr[1], w2 = wr[2], w3 = wr[3];
#pragma unroll
                for (int p = 0; p < 8; p++) {
                    u64t xd = dup2(xr[p]);
                    fma2(acc2[0][p], w0, xd);
                    fma2(acc2[1][p], w1, xd);
                    fma2(acc2[2][p], w2, xd);
                    fma2(acc2[3][p], w3, xd);
                }
            }
        }
        __syncthreads();
    }

    float ns1 = *ns1p;
    int oy = 2 * (m0y + my) + dy;
    float nz[8];
#pragma unroll
    for (int p = 0; p < 8; p++) {
        int ox = 2 * (m0x + p) + dx;
        nz[p] = ns1 * noise1[(n * OH + oy) * OW + ox];
    }
#pragma unroll
    for (int jp = 0; jp < 4; jp++) {
#pragma unroll
        for (int half_ = 0; half_ < 2; half_++) {
            int oc = ob * OCB + ocg * 8 + 2 * jp + half_;
            float isg = g_isg_up[n * CM + oc];
            float bb = b_up[oc];
            float* hp = &g_h[(((size_t)n * CM + oc) * OH + oy) * OW];
#pragma unroll
            for (int p = 0; p < 8; p++) {
                float lo, hi;
                unpack2(acc2[jp][p], lo, hi);
                float a = half_ ? hi : lo;
                int ox = 2 * (m0x + p) + dx;
                float val = fmaf(a, isg, bb) + nz[p];
                val = val > 0.f ? val : 0.2f * val;
                hp[ox] = val;
            }
        }
    }
}

// ---------------------------------------------------------------------------
// Conv2 + to-RGB fused, mma.sync implicit GEMM.
// A halo [180 px][96 k'] built once per ic-chunk; ldmatrix reads it directly
// per tap via per-lane pixel addresses. B double-buffered via cp.async from
// pre-split g_wbs. Epilogue computes h2 AND rgb+bilinear skip.
// ---------------------------------------------------------------------------
#define APITCH 104                               // bf16 units (208B rows)
#define SM_A 0
#define SM_B0 (180 * APITCH * 2)                 // 37440
#define SM_B1 (SM_B0 + CO * APITCH * 2)          // 64064
#define SM_CF (SM_B1 + CO * APITCH * 2)          // 90688
#define SMEM_DYN (SM_CF + 3 * CO * 4 + 64)       // 92288
#define EPIP 133

__global__ __launch_bounds__(256, 2) void k_conv2_mma(
    const float* __restrict__ noise2, const float* __restrict__ b_conv,
    const float* __restrict__ ns2p, const float* __restrict__ y,
    const float* __restrict__ w_rgb, const float* __restrict__ b_rgb,
    float* __restrict__ out, float* __restrict__ yout) {
    extern __shared__ __align__(16) char smem[];
    uint32_t sbase = smem_u32(smem);
    uint32_t sA = sbase + SM_A;
    uint32_t* smA32 = (uint32_t*)(smem + SM_A);
    float* cf = (float*)(smem + SM_CF);

    int tid = threadIdx.x;
    int wid = tid >> 5, lane = tid & 31;
    int wm = wid & 3, wn = wid >> 2;
    int n = blockIdx.z;
    int y0 = blockIdx.y * 8, x0 = blockIdx.x * 16;

    // rgb coefficient table (computed once, region never overwritten)
    if (tid < CO) {
        float s = g_s_rgb[n * CO + tid];
#pragma unroll
        for (int c = 0; c < 3; c++) cf[c * CO + tid] = w_rgb[c * CO + tid] * s;
    }

    // ldmatrix lane roles
    int rowsel = lane & 15;
    int ksel = lane >> 4;
    int apix0 = (wm * 2 + 0) * 18 + rowsel;   // A row pixel base, fragment mi=0
    int apix1 = (wm * 2 + 1) * 18 + rowsel;   // mi=1
    uint32_t sBb[2] = {sbase + SM_B0, sbase + SM_B1};

    // B copy role: 2 threads per oc row, 6 x 16B each
    int cp_oc = tid >> 1, cp_hf = tid & 1;

    float acc[2][8][4];
#pragma unroll
    for (int mi = 0; mi < 2; mi++)
#pragma unroll
        for (int ni = 0; ni < 8; ni++)
#pragma unroll
            for (int q = 0; q < 4; q++) acc[mi][ni][q] = 0.f;

    // prologue: issue B copy for it=0
    {
        const char* src = (const char*)g_wbs + (size_t)cp_oc * 192 + cp_hf * 96;
        uint32_t dst = sBb[0] + cp_oc * 208 + cp_hf * 96;
#pragma unroll
        for (int q = 0; q < 6; q++) cpasync16(dst + q * 16, src + q * 16);
        CP_COMMIT();
    }

    for (int it = 0; it < 54; it++) {
        int c = it / 9, t = it % 9;
        CP_WAIT_ALL();
        __syncthreads();

        if (t == 0) {
            // build split A halo for chunk c: [180 px][96 k'] (hi | lo | hi)
            int ic0 = c * 32;
            for (int e = tid; e < 2880; e += 256) {
                int pix = e % 180;
                int pp = e / 180;            // ic pair 0..15
                int ry = pix / 18, rx = pix % 18;
                int gy = y0 - 1 + ry, gx = x0 - 1 + rx;
                int ic = ic0 + pp * 2;
                float v0 = 0.f, v1 = 0.f;
                if (gy >= 0 && gy < OH && gx >= 0 && gx < OW) {
                    const float* hp = g_h + (((size_t)n * CM + ic) * OH + gy) * OW + gx;
                    v0 = hp[0] * g_s_cv[n * CM + ic];
                    v1 = hp[(size_t)OH * OW] * g_s_cv[n * CM + ic + 1];
                }
                uint32_t p0 = splitpack(v0), p1 = splitpack(v1);
                uint32_t hiP = __byte_perm(p0, p1, 0x5410);
                uint32_t loP = __byte_perm(p0, p1, 0x7632);
                uint32_t* row = smA32 + pix * 52;
                row[pp] = hiP;
                row[16 + pp] = loP;
                row[32 + pp] = hiP;
            }
            __syncthreads();
        }

        // issue B copy for it+1 into the other buffer (readers finished)
        if (it + 1 < 54) {
            const char* src = (const char*)g_wbs +
                ((size_t)(it + 1) * CO * 96) * 2 + (size_t)cp_oc * 192 + cp_hf * 96;
            uint32_t dst = sBb[(it + 1) & 1] + cp_oc * 208 + cp_hf * 96;
#pragma unroll
            for (int q = 0; q < 6; q++) cpasync16(dst + q * 16, src + q * 16);
            CP_COMMIT();
        }

        // mma on buffer it&1, tap (ky,kx)
        int ky = t / 3, kx = t % 3;
        int pixbase = ky * 18 + kx;
        uint32_t sB = sBb[it & 1];
#pragma unroll
        for (int kk = 0; kk < 6; kk++) {
            int koff = kk * 16 + ksel * 8;
            uint32_t ar[2][4];
            ldsm_x4(ar[0], sA + ((pixbase + apix0) * APITCH + koff) * 2);
            ldsm_x4(ar[1], sA + ((pixbase + apix1) * APITCH + koff) * 2);
            uint32_t br[4][4];
#pragma unroll
            for (int nj = 0; nj < 4; nj++)
                ldsm_x4(br[nj], sB + ((wn * 64 + nj * 16 + rowsel) * APITCH + koff) * 2);
#pragma unroll
            for (int mi = 0; mi < 2; mi++)
#pragma unroll
                for (int ni = 0; ni < 8; ni++) {
                    int nj = ni >> 1, pr = ni & 1;
                    mma16816(acc[mi][ni], ar[mi], br[nj][pr], br[nj][pr + 2]);
                }
        }
        __syncthreads();
    }

    // ---- epilogue: raw acc -> smf [128 px][128 oc]
    float* smf = (float*)smem;
#pragma unroll
    for (int mi = 0; mi < 2; mi++)
#pragma unroll
        for (int ni = 0; ni < 8; ni++) {
            int m = wm * 32 + mi * 16 + (lane >> 2);
            int col = wn * 64 + ni * 8 + (lane & 3) * 2;
            smf[m * EPIP + col] = acc[mi][ni][0];
            smf[m * EPIP + col + 1] = acc[mi][ni][1];
            smf[(m + 8) * EPIP + col] = acc[mi][ni][2];
            smf[(m + 8) * EPIP + col + 1] = acc[mi][ni][3];
        }
    __syncthreads();

    // ---- finalize h2: demod + bias + noise + leaky; write out + smf
    {
        int px = tid & 127;
        int ocl = tid >> 7;
        int my = px >> 4, mx = px & 15;
        int yy = y0 + my, xx = x0 + mx;
        float nz = (*ns2p) * noise2[(n * OH + yy) * OW + xx];
        const float* isgp = g_isg_cv + n * CO;
#pragma unroll 4
        for (int ob = 0; ob < 64; ob++) {
            int oc = ob * 2 + ocl;
            float d = smf[px * EPIP + oc];
            float val = fmaf(d, isgp[oc], b_conv[oc]) + nz;
            val = val > 0.f ? val : 0.2f * val;
            smf[px * EPIP + oc] = val;
            out[(((size_t)n * CO + oc) * OH + yy) * OW + xx] = val;
        }
    }
    __syncthreads();

    // ---- fused rgb + bilinear skip (threads 0-127, one per pixel)
    if (tid < 128) {
        int px = tid;
        int my = px >> 4, mx = px & 15;
        int oy = y0 + my, ox = x0 + mx;
        float a0 = b_rgb[0], a1 = b_rgb[1], a2 = b_rgb[2];
        const float* sp = smf + px * EPIP;
#pragma unroll 4
        for (int oc = 0; oc < CO; oc++) {
            float hv = sp[oc];
            a0 = fmaf(hv, cf[oc], a0);
            a1 = fmaf(hv, cf[CO + oc], a1);
            a2 = fmaf(hv, cf[2 * CO + oc], a2);
        }
        a0 = a0 > 0.f ? a0 : 0.2f * a0;
        a1 = a1 > 0.f ? a1 : 0.2f * a1;
        a2 = a2 > 0.f ? a2 : 0.2f * a2;
        float rr[3] = {a0, a1, a2};

        float fy = 0.5f * oy - 0.25f;
        int iyf = (int)floorf(fy);
        float wy = fy - (float)iyf;
        int iy0 = iyf < 0 ? 0 : iyf;
        int iy1 = (iyf + 1) > (HH - 1) ? (HH - 1) : (iyf + 1);
        float fx = 0.5f * ox - 0.25f;
        int ixf = (int)floorf(fx);
        float wx = fx - (float)ixf;
        int ix0 = ixf < 0 ? 0 : ixf;
        int ix1 = (ixf + 1) > (WW - 1) ? (WW - 1) : (ixf + 1);

#pragma unroll
        for (int ch = 0; ch < 3; ch++) {
            const float* yp = y + ((size_t)(n * 3 + ch) * HH) * WW;
            float v00 = yp[iy0 * WW + ix0], v01 = yp[iy0 * WW + ix1];
            float v10 = yp[iy1 * WW + ix0], v11 = yp[iy1 * WW + ix1];
            float vt = v00 + (v01 - v00) * wx;
            float vb = v10 + (v11 - v10) * wx;
            float val = vt + (vb - vt) * wy;
            yout[(((size_t)n * 3 + ch) * OH + oy) * OW + ox] = val + rr[ch];
        }
    }
}

// ---------------------------------------------------------------------------
extern "C" void kernel_launch(void* const* d_in, const int* in_sizes, int n_in,
                              void* d_out, int out_size) {
    const float* x       = (const float*)d_in[0];
    const float* v       = (const float*)d_in[1];
    const float* y       = (const float*)d_in[2];
    const float* noise1  = (const float*)d_in[3];
    const float* noise2  = (const float*)d_in[4];
    const float* w_up    = (const float*)d_in[5];
    const float* b_up    = (const float*)d_in[6];
    const float* sw_up   = (const float*)d_in[7];
    const float* sb_up   = (const float*)d_in[8];
    const float* w_conv  = (const float*)d_in[9];
    const float* b_conv  = (const float*)d_in[10];
    const float* sw_conv = (const float*)d_in[11];
    const float* sb_conv = (const float*)d_in[12];
    const float* w_rgb   = (const float*)d_in[13];
    const float* b_rgb   = (const float*)d_in[14];
    const float* sw_rgb  = (const float*)d_in[15];
    const float* sb_rgb  = (const float*)d_in[16];
    const float* ns1     = (const float*)d_in[17];
    const float* ns2     = (const float*)d_in[18];
    float* out = (float*)d_out;

    (void)in_sizes; (void)n_in; (void)out_size;

    k_transpose<<<1728, 256>>>(w_up, w_conv);
    k_wprep<<<(6 * 9 * CO * 96 + 255) / 256, 256>>>(w_conv);

    dim3 gsu(CI / 8, NB), gsc(CM / 8, NB), gsr(CO / 8, NB);
    k_style<<<gsu, 256>>>(v, sw_up, sb_up, CI, 0);
    k_style<<<gsc, 256>>>(v, sw_conv, sb_conv, CM, 1);
    k_style<<<gsr, 256>>>(v, sw_rgb, sb_rgb, CO, 2);

    dim3 gg0(CM / 4, NB), gg1(CO / 4, NB);
    k_sigma<<<gg0, 128>>>(0);
    k_sigma<<<gg1, 128>>>(1);

    dim3 gup(16, 16, NB * 3);
    k_upconv<<<gup, 256>>>(x, noise1, b_up, ns1);

    cudaFuncSetAttribute(k_conv2_mma, cudaFuncAttributeMaxDynamicSharedMemorySize,
                         SMEM_DYN);
    dim3 gcv(16, 32, NB);
    k_conv2_mma<<<gcv, 256, SMEM_DYN>>>(noise2, b_conv, ns2, y, w_rgb, b_rgb,
                                        out, out + (size_t)NB * CO * OH * OW);
}

// round 6
// speedup vs baseline: 2.8074x; 1.6047x over previous
#include <cuda_runtime.h>
#include <cuda_bf16.h>
#include <math.h>
#include <cstdint>

#define NB 8
#define CI 256
#define CM 192
#define CO 128
#define LV 512
#define HH 128
#define WW 128
#define OH 256
#define OW 256

typedef unsigned long long u64t;

// ===================== warp-MMA helpers (base ISA, sm_80+) =================
__device__ __forceinline__ uint32_t smem_u32(const void* p) {
    uint32_t a;
    asm("{ .reg .u64 t; cvta.to.shared.u64 t, %1; cvt.u32.u64 %0, t; }"
        : "=r"(a) : "l"(p));
    return a;
}
__device__ __forceinline__ void ldsm_x4(uint32_t* r, uint32_t addr) {
    asm volatile("ldmatrix.sync.aligned.m8n8.x4.shared.b16 {%0,%1,%2,%3}, [%4];"
                 : "=r"(r[0]), "=r"(r[1]), "=r"(r[2]), "=r"(r[3]) : "r"(addr));
}
__device__ __forceinline__ void mma16816(float* d, const uint32_t* a,
                                         uint32_t b0, uint32_t b1) {
    asm volatile(
        "mma.sync.aligned.m16n8k16.row.col.f32.bf16.bf16.f32 "
        "{%0,%1,%2,%3}, {%4,%5,%6,%7}, {%8,%9}, {%0,%1,%2,%3};"
        : "+f"(d[0]), "+f"(d[1]), "+f"(d[2]), "+f"(d[3])
        : "r"(a[0]), "r"(a[1]), "r"(a[2]), "r"(a[3]), "r"(b0), "r"(b1));
}
__device__ __forceinline__ void cpasync16(uint32_t dst, const void* src) {
    asm volatile("cp.async.ca.shared.global [%0], [%1], 16;"
                 :: "r"(dst), "l"(src) : "memory");
}
#define CP_COMMIT() asm volatile("cp.async.commit_group;" ::: "memory")
#define CP_WAIT_ALL() asm volatile("cp.async.wait_group 0;" ::: "memory")

// bf16 2-term split: pack (hi | lo<<16)
__device__ __forceinline__ uint32_t splitpack(float v) {
    __nv_bfloat16 h = __float2bfloat16(v);
    float hf = __bfloat162float(h);
    __nv_bfloat16 l = __float2bfloat16(v - hf);
    __nv_bfloat16_raw hr = *(__nv_bfloat16_raw*)&h;
    __nv_bfloat16_raw lr = *(__nv_bfloat16_raw*)&l;
    return (uint32_t)hr.x | ((uint32_t)lr.x << 16);
}

// ===================== device globals ======================================
__device__ float g_h[(size_t)NB * CM * OH * OW];                 // upconv output
__device__ __align__(16) __nv_bfloat16 g_wbs[6 * 9 * CO * 96];   // conv2 B (split)
__device__ __align__(16) __nv_bfloat16 g_wbs_up[9 * 8 * CM * 96];// upconv B (split)
__device__ float g_wsq_up[CM * CI];
__device__ float g_wsq_cv[CO * CM];
__device__ float g_s_up[NB * CI];
__device__ float g_s_cv[NB * CM];
__device__ float g_s_rgb[NB * CO];
__device__ float g_isg_up[NB * CM];
__device__ float g_isg_cv[NB * CO];

// ---------------------------------------------------------------------------
// Fused weight prep: wsq (up+cv), conv2 split B, upconv split B.
// ---------------------------------------------------------------------------
__global__ void k_prep_w(const float* __restrict__ w_up,
                         const float* __restrict__ w_conv) {
    int idx = blockIdx.x * 256 + threadIdx.x;
    if (idx < CM * CI) {                       // wsq_up[o*CI+i], o in CM
        int o = idx / CI, i = idx % CI;
        const float* p = w_up + (i * CM + o) * 9;
        float acc = 0.f;
#pragma unroll
        for (int tt = 0; tt < 9; tt++) acc = fmaf(p[tt], p[tt], acc);
        g_wsq_up[idx] = acc;
    }
    if (idx < CO * CM) {                       // wsq_cv[o*CM+i]
        int o = idx / CM, i = idx % CM;
        const float* p = w_conv + (o * CM + i) * 9;
        float acc = 0.f;
#pragma unroll
        for (int tt = 0; tt < 9; tt++) acc = fmaf(p[tt], p[tt], acc);
        g_wsq_cv[idx] = acc;
    }
    if (idx < 6 * 9 * CO * 96) {               // conv2 B: [c][t][oc][96]
        int k = idx % 96;
        int oc = (idx / 96) % CO;
        int t = (idx / (96 * CO)) % 9;
        int c = idx / (96 * CO * 9);
        int r = k >> 5;
        int ic = c * 32 + (k & 31);
        float w = w_conv[(oc * CM + ic) * 9 + t];
        __nv_bfloat16 hi = __float2bfloat16(w);
        g_wbs[idx] = (r < 2) ? hi : __float2bfloat16(w - __bfloat162float(hi));
    }
    if (idx < 9 * 8 * CM * 96) {               // upconv B: [t][c][oc][96]
        int k = idx % 96;
        int oc = (idx / 96) % CM;
        int c = (idx / (96 * CM)) % 8;
        int t = idx / (96 * CM * 8);
        int r = k >> 5;
        int ic = c * 32 + (k & 31);
        float w = w_up[(ic * CM + oc) * 9 + t];
        __nv_bfloat16 hi = __float2bfloat16(w);
        g_wbs_up[idx] = (r < 2) ? hi : __float2bfloat16(w - __bfloat162float(hi));
    }
}

// ---------------------------------------------------------------------------
// All three styles in one kernel. grid (72, NB), block 256 (8 warps).
// ---------------------------------------------------------------------------
__global__ void k_style_all(const float* __restrict__ v,
                            const float* __restrict__ sw_up, const float* __restrict__ sb_up,
                            const float* __restrict__ sw_cv, const float* __restrict__ sb_cv,
                            const float* __restrict__ sw_rgb, const float* __restrict__ sb_rgb) {
    int warp = threadIdx.x >> 5, lane = threadIdx.x & 31;
    int cg = blockIdx.x * 8 + warp;      // 0..575
    int n = blockIdx.y;
    const float *sw, *sb;
    float* dst;
    int c;
    if (cg < 256)      { sw = sw_up;  sb = sb_up;  dst = g_s_up  + n * CI; c = cg; }
    else if (cg < 448) { sw = sw_cv;  sb = sb_cv;  dst = g_s_cv  + n * CM; c = cg - 256; }
    else               { sw = sw_rgb; sb = sb_rgb; dst = g_s_rgb + n * CO; c = cg - 448; }
    const float* vp = v + n * LV;
    const float* wp = sw + c * LV;
    float acc = 0.f;
#pragma unroll
    for (int l = lane; l < LV; l += 32) acc = fmaf(vp[l], wp[l], acc);
#pragma unroll
    for (int s = 16; s > 0; s >>= 1) acc += __shfl_xor_sync(0xFFFFFFFF, acc, s);
    if (lane == 0) dst[c] = acc + sb[c] + 1.0f;
}

// ---------------------------------------------------------------------------
// Both demodulations in one kernel. grid (80, NB), block 128.
// ---------------------------------------------------------------------------
__global__ void k_sigma_all() {
    int warp = threadIdx.x >> 5, lane = threadIdx.x & 31;
    int og = blockIdx.x * 4 + warp;      // 0..319
    int n = blockIdx.y;
    int IC, o;
    const float *wsq, *s;
    float* dst;
    if (og < CM) { IC = CI; o = og;       wsq = g_wsq_up; s = g_s_up + n * CI; dst = g_isg_up + n * CM; }
    else         { IC = CM; o = og - CM;  wsq = g_wsq_cv; s = g_s_cv + n * CM; dst = g_isg_cv + n * CO; }
    float acc = 0.f;
    for (int i = lane; i < IC; i += 32) {
        float sv = s[i];
        acc = fmaf(sv * sv, wsq[o * IC + i], acc);
    }
#pragma unroll
    for (int sh = 16; sh > 0; sh >>= 1) acc += __shfl_xor_sync(0xFFFFFFFF, acc, sh);
    if (lane == 0) dst[o] = 1.0f / sqrtf(acc + 1e-8f);
}

// ---------------------------------------------------------------------------
// Upconv via mma.sync: parity-decomposed implicit GEMM.
// blockIdx.z = n*4 + cls. M = 128 half-res px (8y x 16x), N = 192 oc.
// A halo [153 px][96 k'] per 32-ic chunk; B cp.async double-buffered.
// 8 warps: 4m x 2n, warp tile 32m x 96n.
// ---------------------------------------------------------------------------
#define UAP 104                               // bf16 pitch (208 B rows)
#define U_SB0 31824                           // 153*208
#define U_SB1 (U_SB0 + CM * UAP * 2)          // +39936
#define U_SMEM (U_SB1 + CM * UAP * 2)         // 111696
#define U_EPIP 197

__device__ __forceinline__ void upc_issueB(uint32_t dstBase, const char* src, int tid) {
#pragma unroll
    for (int e = 0; e < 9; e++) {
        int ee = tid + e * 256;
        int row = ee / 12, q = ee % 12;
        cpasync16(dstBase + row * 208 + q * 16, src + row * 192 + q * 16);
    }
    CP_COMMIT();
}

__global__ __launch_bounds__(256, 1) void k_upconv_mma(
    const float* __restrict__ x, const float* __restrict__ noise1,
    const float* __restrict__ b_up, const float* __restrict__ ns1p) {
    extern __shared__ __align__(16) char smem[];
    uint32_t sbase = smem_u32(smem);
    uint32_t sA = sbase;
    uint32_t* smA32 = (uint32_t*)smem;

    int tid = threadIdx.x;
    int wid = tid >> 5, lane = tid & 31;
    int wm = wid & 3, wn = wid >> 2;
    int zc = blockIdx.z;
    int n = zc >> 2, cls = zc & 3;
    int y0 = blockIdx.y * 8, x0 = blockIdx.x * 16;   // half-res tile origin

    // tap tables per parity class
    int nt, tapid[4], offy[4], offx[4];
    if (cls == 0) {
        nt = 1; tapid[0] = 4; offy[0] = 0; offx[0] = 0;
    } else if (cls == 1) {
        nt = 2;
        tapid[0] = 3; offy[0] = 0; offx[0] = 1;
        tapid[1] = 5; offy[1] = 0; offx[1] = 0;
    } else if (cls == 2) {
        nt = 2;
        tapid[0] = 1; offy[0] = 1; offx[0] = 0;
        tapid[1] = 7; offy[1] = 0; offx[1] = 0;
    } else {
        nt = 4;
        tapid[0] = 0; offy[0] = 1; offx[0] = 1;
        tapid[1] = 2; offy[1] = 1; offx[1] = 0;
        tapid[2] = 6; offy[2] = 0; offx[2] = 1;
        tapid[3] = 8; offy[3] = 0; offx[3] = 0;
    }
    int NIT = nt * 8;

    uint32_t sBb[2] = {sbase + U_SB0, sbase + U_SB1};
    int rowsel = lane & 15, ksel = lane >> 4;

    float acc[2][12][4];
#pragma unroll
    for (int mi = 0; mi < 2; mi++)
#pragma unroll
        for (int ni = 0; ni < 12; ni++)
#pragma unroll
            for (int q = 0; q < 4; q++) acc[mi][ni][q] = 0.f;

    // prologue: B for iteration 0 (tap tapid[0], chunk 0)
    upc_issueB(sBb[0], (const char*)g_wbs_up + (size_t)(tapid[0] * 8) * 36864, tid);

    for (int it = 0; it < NIT; it++) {
        int c = it / nt, ti = it % nt;
        CP_WAIT_ALL();
        __syncthreads();

        if (ti == 0) {
            // build split A halo for chunk c: [153 px][96 k'] (hi | lo | hi)
            int ic0 = c * 32;
            for (int e = tid; e < 2448; e += 256) {
                int pix = e % 153;
                int pp = e / 153;                 // ic pair 0..15
                int ry = pix / 17, rx = pix % 17;
                int gy = y0 + ry, gx = x0 + rx;
                int ic = ic0 + pp * 2;
                float v0 = 0.f, v1 = 0.f;
                if (gy < HH && gx < WW) {
                    const float* xp = x + (((size_t)n * CI + ic) * HH + gy) * WW + gx;
                    v0 = xp[0] * g_s_up[n * CI + ic];
                    v1 = xp[(size_t)HH * WW] * g_s_up[n * CI + ic + 1];
                }
                uint32_t p0 = splitpack(v0), p1 = splitpack(v1);
                uint32_t hiP = __byte_perm(p0, p1, 0x5410);
                uint32_t loP = __byte_perm(p0, p1, 0x7632);
                uint32_t* row = smA32 + pix * 52;
                row[pp] = hiP;
                row[16 + pp] = loP;
                row[32 + pp] = hiP;
            }
            __syncthreads();
        }

        // prefetch next B
        if (it + 1 < NIT) {
            int c2 = (it + 1) / nt, ti2 = (it + 1) % nt;
            upc_issueB(sBb[(it + 1) & 1],
                       (const char*)g_wbs_up + (size_t)(tapid[ti2] * 8 + c2) * 36864,
                       tid);
        }

        // mma on current buffer
        uint32_t sB = sBb[it & 1];
        int ap0 = (wm * 2 + 0 + offy[ti]) * 17 + offx[ti] + rowsel;
        int ap1 = (wm * 2 + 1 + offy[ti]) * 17 + offx[ti] + rowsel;
#pragma unroll
        for (int kk = 0; kk < 6; kk++) {
            int koff = kk * 16 + ksel * 8;
            uint32_t ar[2][4];
            ldsm_x4(ar[0], sA + (ap0 * UAP + koff) * 2);
            ldsm_x4(ar[1], sA + (ap1 * UAP + koff) * 2);
            uint32_t br[6][4];
#pragma unroll
            for (int nj = 0; nj < 6; nj++)
                ldsm_x4(br[nj], sB + ((wn * 96 + nj * 16 + rowsel) * UAP + koff) * 2);
#pragma unroll
            for (int mi = 0; mi < 2; mi++)
#pragma unroll
                for (int ni = 0; ni < 12; ni++) {
                    int nj = ni >> 1, pr = ni & 1;
                    mma16816(acc[mi][ni], ar[mi], br[nj][pr], br[nj][pr + 2]);
                }
        }
        __syncthreads();
    }

    // ---- epilogue: acc -> smf [128 px][192 oc]
    float* smf = (float*)smem;
#pragma unroll
    for (int mi = 0; mi < 2; mi++)
#pragma unroll
        for (int ni = 0; ni < 12; ni++) {
            int m = wm * 32 + mi * 16 + (lane >> 2);
            int col = wn * 96 + ni * 8 + (lane & 3) * 2;
            smf[m * U_EPIP + col] = acc[mi][ni][0];
            smf[m * U_EPIP + col + 1] = acc[mi][ni][1];
            smf[(m + 8) * U_EPIP + col] = acc[mi][ni][2];
            smf[(m + 8) * U_EPIP + col + 1] = acc[mi][ni][3];
        }
    __syncthreads();

    // ---- finalize h: demod + bias + noise + leaky; scatter to parity slot
    {
        int px = tid & 127;
        int ocl = tid >> 7;
        int my = px >> 4, mx = px & 15;
        int oy = 2 * (y0 + my) + (cls >> 1);
        int ox = 2 * (x0 + mx) + (cls & 1);
        float nz = (*ns1p) * noise1[(n * OH + oy) * OW + ox];
        const float* isgp = g_isg_up + n * CM;
#pragma unroll 4
        for (int ob = 0; ob < 96; ob++) {
            int oc = ob * 2 + ocl;
            float d = smf[px * U_EPIP + oc];
            float val = fmaf(d, isgp[oc], b_up[oc]) + nz;
            val = val > 0.f ? val : 0.2f * val;
            g_h[(((size_t)n * CM + oc) * OH + oy) * OW + ox] = val;
        }
    }
}

// ---------------------------------------------------------------------------
// Conv2 + to-RGB fused, mma.sync implicit GEMM (unchanged from Round 5).
// ---------------------------------------------------------------------------
#define APITCH 104
#define SM_A 0
#define SM_B0 (180 * APITCH * 2)
#define SM_B1 (SM_B0 + CO * APITCH * 2)
#define SM_CF (SM_B1 + CO * APITCH * 2)
#define SMEM_DYN (SM_CF + 3 * CO * 4 + 64)
#define EPIP 133

__global__ __launch_bounds__(256, 2) void k_conv2_mma(
    const float* __restrict__ noise2, const float* __restrict__ b_conv,
    const float* __restrict__ ns2p, const float* __restrict__ y,
    const float* __restrict__ w_rgb, const float* __restrict__ b_rgb,
    float* __restrict__ out, float* __restrict__ yout) {
    extern __shared__ __align__(16) char smem[];
    uint32_t sbase = smem_u32(smem);
    uint32_t sA = sbase + SM_A;
    uint32_t* smA32 = (uint32_t*)(smem + SM_A);
    float* cf = (float*)(smem + SM_CF);

    int tid = threadIdx.x;
    int wid = tid >> 5, lane = tid & 31;
    int wm = wid & 3, wn = wid >> 2;
    int n = blockIdx.z;
    int y0 = blockIdx.y * 8, x0 = blockIdx.x * 16;

    if (tid < CO) {
        float s = g_s_rgb[n * CO + tid];
#pragma unroll
        for (int c = 0; c < 3; c++) cf[c * CO + tid] = w_rgb[c * CO + tid] * s;
    }

    int rowsel = lane & 15;
    int ksel = lane >> 4;
    int apix0 = (wm * 2 + 0) * 18 + rowsel;
    int apix1 = (wm * 2 + 1) * 18 + rowsel;
    uint32_t sBb[2] = {sbase + SM_B0, sbase + SM_B1};

    int cp_oc = tid >> 1, cp_hf = tid & 1;

    float acc[2][8][4];
#pragma unroll
    for (int mi = 0; mi < 2; mi++)
#pragma unroll
        for (int ni = 0; ni < 8; ni++)
#pragma unroll
            for (int q = 0; q < 4; q++) acc[mi][ni][q] = 0.f;

    {
        const char* src = (const char*)g_wbs + (size_t)cp_oc * 192 + cp_hf * 96;
        uint32_t dst = sBb[0] + cp_oc * 208 + cp_hf * 96;
#pragma unroll
        for (int q = 0; q < 6; q++) cpasync16(dst + q * 16, src + q * 16);
        CP_COMMIT();
    }

    for (int it = 0; it < 54; it++) {
        int c = it / 9, t = it % 9;
        CP_WAIT_ALL();
        __syncthreads();

        if (t == 0) {
            int ic0 = c * 32;
            for (int e = tid; e < 2880; e += 256) {
                int pix = e % 180;
                int pp = e / 180;
                int ry = pix / 18, rx = pix % 18;
                int gy = y0 - 1 + ry, gx = x0 - 1 + rx;
                int ic = ic0 + pp * 2;
                float v0 = 0.f, v1 = 0.f;
                if (gy >= 0 && gy < OH && gx >= 0 && gx < OW) {
                    const float* hp = g_h + (((size_t)n * CM + ic) * OH + gy) * OW + gx;
                    v0 = hp[0] * g_s_cv[n * CM + ic];
                    v1 = hp[(size_t)OH * OW] * g_s_cv[n * CM + ic + 1];
                }
                uint32_t p0 = splitpack(v0), p1 = splitpack(v1);
                uint32_t hiP = __byte_perm(p0, p1, 0x5410);
                uint32_t loP = __byte_perm(p0, p1, 0x7632);
                uint32_t* row = smA32 + pix * 52;
                row[pp] = hiP;
                row[16 + pp] = loP;
                row[32 + pp] = hiP;
            }
            __syncthreads();
        }

        if (it + 1 < 54) {
            const char* src = (const char*)g_wbs +
                ((size_t)(it + 1) * CO * 96) * 2 + (size_t)cp_oc * 192 + cp_hf * 96;
            uint32_t dst = sBb[(it + 1) & 1] + cp_oc * 208 + cp_hf * 96;
#pragma unroll
            for (int q = 0; q < 6; q++) cpasync16(dst + q * 16, src + q * 16);
            CP_COMMIT();
        }

        int ky = (it % 9) / 3, kx = (it % 9) % 3;
        int pixbase = ky * 18 + kx;
        uint32_t sB = sBb[it & 1];
#pragma unroll
        for (int kk = 0; kk < 6; kk++) {
            int koff = kk * 16 + ksel * 8;
            uint32_t ar[2][4];
            ldsm_x4(ar[0], sA + ((pixbase + apix0) * APITCH + koff) * 2);
            ldsm_x4(ar[1], sA + ((pixbase + apix1) * APITCH + koff) * 2);
            uint32_t br[4][4];
#pragma unroll
            for (int nj = 0; nj < 4; nj++)
                ldsm_x4(br[nj], sB + ((wn * 64 + nj * 16 + rowsel) * APITCH + koff) * 2);
#pragma unroll
            for (int mi = 0; mi < 2; mi++)
#pragma unroll
                for (int ni = 0; ni < 8; ni++) {
                    int nj = ni >> 1, pr = ni & 1;
                    mma16816(acc[mi][ni], ar[mi], br[nj][pr], br[nj][pr + 2]);
                }
        }
        __syncthreads();
    }

    float* smf = (float*)smem;
#pragma unroll
    for (int mi = 0; mi < 2; mi++)
#pragma unroll
        for (int ni = 0; ni < 8; ni++) {
            int m = wm * 32 + mi * 16 + (lane >> 2);
            int col = wn * 64 + ni * 8 + (lane & 3) * 2;
            smf[m * EPIP + col] = acc[mi][ni][0];
            smf[m * EPIP + col + 1] = acc[mi][ni][1];
            smf[(m + 8) * EPIP + col] = acc[mi][ni][2];
            smf[(m + 8) * EPIP + col + 1] = acc[mi][ni][3];
        }
    __syncthreads();

    {
        int px = tid & 127;
        int ocl = tid >> 7;
        int my = px >> 4, mx = px & 15;
        int yy = y0 + my, xx = x0 + mx;
        float nz = (*ns2p) * noise2[(n * OH + yy) * OW + xx];
        const float* isgp = g_isg_cv + n * CO;
#pragma unroll 4
        for (int ob = 0; ob < 64; ob++) {
            int oc = ob * 2 + ocl;
            float d = smf[px * EPIP + oc];
            float val = fmaf(d, isgp[oc], b_conv[oc]) + nz;
            val = val > 0.f ? val : 0.2f * val;
            smf[px * EPIP + oc] = val;
            out[(((size_t)n * CO + oc) * OH + yy) * OW + xx] = val;
        }
    }
    __syncthreads();

    if (tid < 128) {
        int px = tid;
        int my = px >> 4, mx = px & 15;
        int oy = y0 + my, ox = x0 + mx;
        float a0 = b_rgb[0], a1 = b_rgb[1], a2 = b_rgb[2];
        const float* sp = smf + px * EPIP;
#pragma unroll 4
        for (int oc = 0; oc < CO; oc++) {
            float hv = sp[oc];
            a0 = fmaf(hv, cf[oc], a0);
            a1 = fmaf(hv, cf[CO + oc], a1);
            a2 = fmaf(hv, cf[2 * CO + oc], a2);
        }
        a0 = a0 > 0.f ? a0 : 0.2f * a0;
        a1 = a1 > 0.f ? a1 : 0.2f * a1;
        a2 = a2 > 0.f ? a2 : 0.2f * a2;
        float rr[3] = {a0, a1, a2};

        float fy = 0.5f * oy - 0.25f;
        int iyf = (int)floorf(fy);
        float wy = fy - (float)iyf;
        int iy0 = iyf < 0 ? 0 : iyf;
        int iy1 = (iyf + 1) > (HH - 1) ? (HH - 1) : (iyf + 1);
        float fx = 0.5f * ox - 0.25f;
        int ixf = (int)floorf(fx);
        float wx = fx - (float)ixf;
        int ix0 = ixf < 0 ? 0 : ixf;
        int ix1 = (ixf + 1) > (WW - 1) ? (WW - 1) : (ixf + 1);

#pragma unroll
        for (int ch = 0; ch < 3; ch++) {
            const float* yp = y + ((size_t)(n * 3 + ch) * HH) * WW;
            float v00 = yp[iy0 * WW + ix0], v01 = yp[iy0 * WW + ix1];
            float v10 = yp[iy1 * WW + ix0], v11 = yp[iy1 * WW + ix1];
            float vt = v00 + (v01 - v00) * wx;
            float vb = v10 + (v11 - v10) * wx;
            float val = vt + (vb - vt) * wy;
            yout[(((size_t)n * 3 + ch) * OH + oy) * OW + ox] = val + rr[ch];
        }
    }
}

// ---------------------------------------------------------------------------
extern "C" void kernel_launch(void* const* d_in, const int* in_sizes, int n_in,
                              void* d_out, int out_size) {
    const float* x       = (const float*)d_in[0];
    const float* v       = (const float*)d_in[1];
    const float* y       = (const float*)d_in[2];
    const float* noise1  = (const float*)d_in[3];
    const float* noise2  = (const float*)d_in[4];
    const float* w_up    = (const float*)d_in[5];
    const float* b_up    = (const float*)d_in[6];
    const float* sw_up   = (const float*)d_in[7];
    const float* sb_up   = (const float*)d_in[8];
    const float* w_conv  = (const float*)d_in[9];
    const float* b_conv  = (const float*)d_in[10];
    const float* sw_conv = (const float*)d_in[11];
    const float* sb_conv = (const float*)d_in[12];
    const float* w_rgb   = (const float*)d_in[13];
    const float* b_rgb   = (const float*)d_in[14];
    const float* sw_rgb  = (const float*)d_in[15];
    const float* sb_rgb  = (const float*)d_in[16];
    const float* ns1     = (const float*)d_in[17];
    const float* ns2     = (const float*)d_in[18];
    float* out = (float*)d_out;

    (void)in_sizes; (void)n_in; (void)out_size;

    k_prep_w<<<(9 * 8 * CM * 96 + 255) / 256, 256>>>(w_up, w_conv);

    dim3 gst(72, NB);
    k_style_all<<<gst, 256>>>(v, sw_up, sb_up, sw_conv, sb_conv, sw_rgb, sb_rgb);

    dim3 gsg(80, NB);
    k_sigma_all<<<gsg, 128>>>();

    cudaFuncSetAttribute(k_upconv_mma, cudaFuncAttributeMaxDynamicSharedMemorySize,
                         U_SMEM);
    dim3 gup(8, 16, NB * 4);
    k_upconv_mma<<<gup, 256, U_SMEM>>>(x, noise1, b_up, ns1);

    cudaFuncSetAttribute(k_conv2_mma, cudaFuncAttributeMaxDynamicSharedMemorySize,
                         SMEM_DYN);
    dim3 gcv(16, 32, NB);
    k_conv2_mma<<<gcv, 256, SMEM_DYN>>>(noise2, b_conv, ns2, y, w_rgb, b_rgb,
                                        out, out + (size_t)NB * CO * OH * OW);
}

// round 7
// speedup vs baseline: 2.8549x; 1.0169x over previous
#include <cuda_runtime.h>
#include <cuda_bf16.h>
#include <math.h>
#include <cstdint>

#define NB 8
#define CI 256
#define CM 192
#define CO 128
#define LV 512
#define HH 128
#define WW 128
#define OH 256
#define OW 256

// ===================== warp-MMA helpers (base ISA, sm_80+) =================
__device__ __forceinline__ uint32_t smem_u32(const void* p) {
    uint32_t a;
    asm("{ .reg .u64 t; cvta.to.shared.u64 t, %1; cvt.u32.u64 %0, t; }"
        : "=r"(a) : "l"(p));
    return a;
}
__device__ __forceinline__ void ldsm_x4(uint32_t* r, uint32_t addr) {
    asm volatile("ldmatrix.sync.aligned.m8n8.x4.shared.b16 {%0,%1,%2,%3}, [%4];"
                 : "=r"(r[0]), "=r"(r[1]), "=r"(r[2]), "=r"(r[3]) : "r"(addr));
}
__device__ __forceinline__ void mma16816(float* d, const uint32_t* a,
                                         uint32_t b0, uint32_t b1) {
    asm volatile(
        "mma.sync.aligned.m16n8k16.row.col.f32.bf16.bf16.f32 "
        "{%0,%1,%2,%3}, {%4,%5,%6,%7}, {%8,%9}, {%0,%1,%2,%3};"
        : "+f"(d[0]), "+f"(d[1]), "+f"(d[2]), "+f"(d[3])
        : "r"(a[0]), "r"(a[1]), "r"(a[2]), "r"(a[3]), "r"(b0), "r"(b1));
}
__device__ __forceinline__ void cpasync16(uint32_t dst, const void* src) {
    asm volatile("cp.async.ca.shared.global [%0], [%1], 16;"
                 :: "r"(dst), "l"(src) : "memory");
}
__device__ __forceinline__ void cpasync16p(uint32_t dst, const void* src, uint32_t sz) {
    asm volatile("cp.async.ca.shared.global [%0], [%1], 16, %2;"
                 :: "r"(dst), "l"(src), "r"(sz) : "memory");
}
#define CP_COMMIT() asm volatile("cp.async.commit_group;" ::: "memory")
#define CP_WAIT2() asm volatile("cp.async.wait_group 2;" ::: "memory")
#define CP_WAIT0() asm volatile("cp.async.wait_group 0;" ::: "memory")

// truncation split of two f32 -> (hi-pair, lo-pair) packed bf16x2
__device__ __forceinline__ void split2(float h0, float h1, uint32_t& hiP, uint32_t& loP) {
    uint32_t b0 = __float_as_uint(h0), b1 = __float_as_uint(h1);
    hiP = __byte_perm(b0, b1, 0x7632);
    float r0 = h0 - __uint_as_float(b0 & 0xFFFF0000u);
    float r1 = h1 - __uint_as_float(b1 & 0xFFFF0000u);
    asm("cvt.rn.bf16x2.f32 %0, %1, %2;" : "=r"(loP) : "f"(r1), "f"(r0));
}

// ===================== device globals ======================================
__device__ float g_ht[(size_t)NB * OH * OW * CM];                    // h, px-major
__device__ __align__(16) __nv_bfloat16 g_xsp[(size_t)NB * 8 * HH * WW * 96];   // split x
__device__ __align__(16) __nv_bfloat16 g_hs[(size_t)NB * 6 * OH * OW * 96];    // split h*s_cv
__device__ __align__(16) __nv_bfloat16 g_wbs[6 * 9 * CO * 96];       // conv2 B (split)
__device__ __align__(16) __nv_bfloat16 g_wbs_up[9 * 8 * CM * 96];    // upconv B (split)
__device__ float g_wsq_up[CM * CI];
__device__ float g_wsq_cv[CO * CM];
__device__ float g_s_up[NB * CI];
__device__ float g_s_cv[NB * CM];
__device__ float g_s_rgb[NB * CO];
__device__ float g_isg_up[NB * CM];
__device__ float g_isg_cv[NB * CO];

// ---------------------------------------------------------------------------
// Weight prep: wsq (up+cv), conv2 split B, upconv split B.
// ---------------------------------------------------------------------------
__global__ void k_prep_w(const float* __restrict__ w_up,
                         const float* __restrict__ w_conv) {
    int idx = blockIdx.x * 256 + threadIdx.x;
    if (idx < CM * CI) {
        int o = idx / CI, i = idx % CI;
        const float* p = w_up + (i * CM + o) * 9;
        float acc = 0.f;
#pragma unroll
        for (int tt = 0; tt < 9; tt++) acc = fmaf(p[tt], p[tt], acc);
        g_wsq_up[idx] = acc;
    }
    if (idx < CO * CM) {
        int o = idx / CM, i = idx % CM;
        const float* p = w_conv + (o * CM + i) * 9;
        float acc = 0.f;
#pragma unroll
        for (int tt = 0; tt < 9; tt++) acc = fmaf(p[tt], p[tt], acc);
        g_wsq_cv[idx] = acc;
    }
    if (idx < 6 * 9 * CO * 96) {               // conv2 B: [c][t][oc][96]
        int k = idx % 96;
        int oc = (idx / 96) % CO;
        int t = (idx / (96 * CO)) % 9;
        int c = idx / (96 * CO * 9);
        int r = k >> 5;
        int ic = c * 32 + (k & 31);
        float w = w_conv[(oc * CM + ic) * 9 + t];
        __nv_bfloat16 hi = __float2bfloat16(w);
        g_wbs[idx] = (r < 2) ? hi : __float2bfloat16(w - __bfloat162float(hi));
    }
    if (idx < 9 * 8 * CM * 96) {               // upconv B: [t][c][oc][96]
        int k = idx % 96;
        int oc = (idx / 96) % CM;
        int c = (idx / (96 * CM)) % 8;
        int t = idx / (96 * CM * 8);
        int r = k >> 5;
        int ic = c * 32 + (k & 31);
        float w = w_up[(ic * CM + oc) * 9 + t];
        __nv_bfloat16 hi = __float2bfloat16(w);
        g_wbs_up[idx] = (r < 2) ? hi : __float2bfloat16(w - __bfloat162float(hi));
    }
}

// ---------------------------------------------------------------------------
__global__ void k_style_all(const float* __restrict__ v,
                            const float* __restrict__ sw_up, const float* __restrict__ sb_up,
                            const float* __restrict__ sw_cv, const float* __restrict__ sb_cv,
                            const float* __restrict__ sw_rgb, const float* __restrict__ sb_rgb) {
    int warp = threadIdx.x >> 5, lane = threadIdx.x & 31;
    int cg = blockIdx.x * 8 + warp;
    int n = blockIdx.y;
    const float *sw, *sb;
    float* dst;
    int c;
    if (cg < 256)      { sw = sw_up;  sb = sb_up;  dst = g_s_up  + n * CI; c = cg; }
    else if (cg < 448) { sw = sw_cv;  sb = sb_cv;  dst = g_s_cv  + n * CM; c = cg - 256; }
    else               { sw = sw_rgb; sb = sb_rgb; dst = g_s_rgb + n * CO; c = cg - 448; }
    const float* vp = v + n * LV;
    const float* wp = sw + c * LV;
    float acc = 0.f;
#pragma unroll
    for (int l = lane; l < LV; l += 32) acc = fmaf(vp[l], wp[l], acc);
#pragma unroll
    for (int s = 16; s > 0; s >>= 1) acc += __shfl_xor_sync(0xFFFFFFFF, acc, s);
    if (lane == 0) dst[c] = acc + sb[c] + 1.0f;
}

// ---------------------------------------------------------------------------
__global__ void k_sigma_all() {
    int warp = threadIdx.x >> 5, lane = threadIdx.x & 31;
    int og = blockIdx.x * 4 + warp;
    int n = blockIdx.y;
    int IC, o;
    const float *wsq, *s;
    float* dst;
    if (og < CM) { IC = CI; o = og;       wsq = g_wsq_up; s = g_s_up + n * CI; dst = g_isg_up + n * CM; }
    else         { IC = CM; o = og - CM;  wsq = g_wsq_cv; s = g_s_cv + n * CM; dst = g_isg_cv + n * CO; }
    float acc = 0.f;
    for (int i = lane; i < IC; i += 32) {
        float sv = s[i];
        acc = fmaf(sv * sv, wsq[o * IC + i], acc);
    }
#pragma unroll
    for (int sh = 16; sh > 0; sh >>= 1) acc += __shfl_xor_sync(0xFFFFFFFF, acc, sh);
    if (lane == 0) dst[o] = 1.0f / sqrtf(acc + 1e-8f);
}

// ---------------------------------------------------------------------------
// x pre-split: g_xsp[n][c][py][px][96] = split(x * s_up), 3 regions (hi,lo,hi).
// grid (128 py, 8 c, NB), block 256.
// ---------------------------------------------------------------------------
__global__ void k_xsplit(const float* __restrict__ x) {
    __shared__ float sm[32][129];
    int py = blockIdx.x, c = blockIdx.y, n = blockIdx.z;
    int tid = threadIdx.x;
    for (int e = tid; e < 4096; e += 256) {
        int ic = e >> 7, px = e & 127;
        sm[ic][px] = x[(((size_t)n * CI + c * 32 + ic) << 14) + (py << 7) + px] *
                     g_s_up[n * CI + c * 32 + ic];
    }
    __syncthreads();
    int px = tid >> 1, hf = tid & 1;
    uint32_t hi[8], lo[8];
#pragma unroll
    for (int j = 0; j < 8; j++) {
        int p = hf * 8 + j;
        split2(sm[2 * p][px], sm[2 * p + 1][px], hi[j], lo[j]);
    }
    uint4* d4 = (uint4*)((uint32_t*)g_xsp +
                         ((size_t)(n * 8 + c) * 16384 + py * 128 + px) * 48);
    uint4 v0 = make_uint4(hi[0], hi[1], hi[2], hi[3]);
    uint4 v1 = make_uint4(hi[4], hi[5], hi[6], hi[7]);
    uint4 w0 = make_uint4(lo[0], lo[1], lo[2], lo[3]);
    uint4 w1 = make_uint4(lo[4], lo[5], lo[6], lo[7]);
    d4[hf * 2 + 0] = v0; d4[hf * 2 + 1] = v1;
    d4[4 + hf * 2 + 0] = w0; d4[4 + hf * 2 + 1] = w1;
    d4[8 + hf * 2 + 0] = v0; d4[8 + hf * 2 + 1] = v1;
}

// ---------------------------------------------------------------------------
// h pre-split: g_hs[n][c][py][px][96] = split(h * s_cv).
// grid (4096, 6, NB), block 256.
// ---------------------------------------------------------------------------
__global__ void k_hsplit() {
    int tid = threadIdx.x;
    int p = tid & 15, pxl = tid >> 4;
    int pxg = blockIdx.x * 16 + pxl;
    int c = blockIdx.y, n = blockIdx.z;
    int ic = c * 32 + 2 * p;
    const float* hp = g_ht + ((size_t)n * 65536 + pxg) * CM + ic;
    float h0 = hp[0] * g_s_cv[n * CM + ic];
    float h1 = hp[1] * g_s_cv[n * CM + ic + 1];
    uint32_t hiP, loP;
    split2(h0, h1, hiP, loP);
    uint32_t* dst = (uint32_t*)g_hs + ((size_t)(n * 6 + c) * 65536 + pxg) * 48 + p;
    dst[0] = hiP;
    dst[16] = loP;
    dst[32] = hiP;
}

// ---------------------------------------------------------------------------
// Upconv via mma.sync: parity-decomposed implicit GEMM, fully async-staged.
// A ring-of-3 (chunk prefetch +2), B ring-of-3 (tap prefetch +2), 1 barrier/tap.
// ---------------------------------------------------------------------------
#define U_ABUF (153 * 208)
#define U_BBUF (192 * 208)
#define U_B0   (3 * U_ABUF)
#define U_SMEM (3 * U_ABUF + 3 * U_BBUF)      // 215280
#define UAP 104
#define U_EPIP 200

__global__ __launch_bounds__(256, 1) void k_upconv_mma(
    const float* __restrict__ noise1, const float* __restrict__ b_up,
    const float* __restrict__ ns1p) {
    extern __shared__ __align__(16) char smem[];
    uint32_t sbase = smem_u32(smem);

    int tid = threadIdx.x;
    int wid = tid >> 5, lane = tid & 31;
    int wm = wid & 3, wn = wid >> 2;
    int zc = blockIdx.z;
    int n = zc >> 2, cls = zc & 3;
    int y0 = blockIdx.y * 8, x0 = blockIdx.x * 16;

    int nt, ntsh, tapid[4], pixoff[4];
    if (cls == 0) {
        nt = 1; ntsh = 0;
        tapid[0] = 4; pixoff[0] = 0;
    } else if (cls == 1) {
        nt = 2; ntsh = 1;
        tapid[0] = 3; pixoff[0] = 1;          // offy=0 offx=1
        tapid[1] = 5; pixoff[1] = 0;
    } else if (cls == 2) {
        nt = 2; ntsh = 1;
        tapid[0] = 1; pixoff[0] = 17;         // offy=1 offx=0
        tapid[1] = 7; pixoff[1] = 0;
    } else {
        nt = 4; ntsh = 2;
        tapid[0] = 0; pixoff[0] = 18;
        tapid[1] = 2; pixoff[1] = 17;
        tapid[2] = 6; pixoff[2] = 1;
        tapid[3] = 8; pixoff[3] = 0;
    }
    const int NIT = nt * 8;

    int rowsel = lane & 15, ksel = lane >> 4;

    auto issueA = [&](int cc) {
        const char* asrc = (const char*)g_xsp + ((size_t)(n * 8 + cc) * 16384) * 192;
        uint32_t abuf = sbase + (cc % 3) * U_ABUF;
        for (int e = tid; e < 1836; e += 256) {
            int pix = e / 12, q = e % 12;
            int ry = pix / 17, rx = pix % 17;
            int gy = y0 + ry, gx = x0 + rx;
            uint32_t ok = (gy < HH && gx < WW) ? 16u : 0u;
            int gyc = gy < HH - 1 ? gy : HH - 1;
            int gxc = gx < WW - 1 ? gx : WW - 1;
            cpasync16p(abuf + pix * 208 + q * 16,
                       asrc + ((size_t)gyc * 128 + gxc) * 192 + q * 16, ok);
        }
    };
    auto issueB = [&](int it2) {
        int c2 = it2 >> ntsh, ti2 = it2 & (nt - 1);
        const char* bsrc = (const char*)g_wbs_up + (size_t)(tapid[ti2] * 8 + c2) * 36864;
        uint32_t bbuf = sbase + U_B0 + (it2 % 3) * U_BBUF;
#pragma unroll
        for (int e = 0; e < 9; e++) {
            int ee = tid + e * 256;
            int row = ee / 12, q = ee % 12;
            cpasync16(bbuf + row * 208 + q * 16, bsrc + row * 192 + q * 16);
        }
    };

    float acc[2][12][4];
#pragma unroll
    for (int mi = 0; mi < 2; mi++)
#pragma unroll
        for (int ni = 0; ni < 12; ni++)
#pragma unroll
            for (int q = 0; q < 4; q++) acc[mi][ni][q] = 0.f;

    // prologue: 4 groups = [A0][B0][A1][B1]
    issueA(0); CP_COMMIT();
    issueB(0); CP_COMMIT();
    issueA(1); CP_COMMIT();
    issueB(1); CP_COMMIT();

    for (int it = 0; it < NIT; it++) {
        int c = it >> ntsh, ti = it & (nt - 1);
        CP_WAIT2();
        __syncthreads();

        // commit slot 1: A prefetch (chunk start) or empty
        if (ti == 0 && c + 2 < 8) issueA(c + 2);
        CP_COMMIT();
        // commit slot 2: B prefetch or empty
        if (it + 2 < NIT) issueB(it + 2);
        CP_COMMIT();

        uint32_t sA = sbase + (c % 3) * U_ABUF;
        uint32_t sB = sbase + U_B0 + (it % 3) * U_BBUF;
        int ap0 = ((wm * 2 + 0) * 17 + rowsel + pixoff[ti]) * 208;
        int ap1 = ((wm * 2 + 1) * 17 + rowsel + pixoff[ti]) * 208;
#pragma unroll
        for (int kk = 0; kk < 6; kk++) {
            int koff = (kk * 16 + ksel * 8) * 2;
            uint32_t ar[2][4];
            ldsm_x4(ar[0], sA + ap0 + koff);
            ldsm_x4(ar[1], sA + ap1 + koff);
            uint32_t br[6][4];
#pragma unroll
            for (int nj = 0; nj < 6; nj++)
                ldsm_x4(br[nj], sB + (wn * 96 + nj * 16 + rowsel) * 208 + koff);
#pragma unroll
            for (int mi = 0; mi < 2; mi++)
#pragma unroll
                for (int ni = 0; ni < 12; ni++) {
                    int nj = ni >> 1, pr = ni & 1;
                    mma16816(acc[mi][ni], ar[mi], br[nj][pr], br[nj][pr + 2]);
                }
        }
        __syncthreads();
    }

    CP_WAIT0();
    __syncthreads();

    // ---- epilogue: acc -> smf [128 px][192 oc] (pitch 200)
    float* smf = (float*)smem;
#pragma unroll
    for (int mi = 0; mi < 2; mi++)
#pragma unroll
        for (int ni = 0; ni < 12; ni++) {
            int m = wm * 32 + mi * 16 + (lane >> 2);
            int col = wn * 96 + ni * 8 + (lane & 3) * 2;
            smf[m * U_EPIP + col] = acc[mi][ni][0];
            smf[m * U_EPIP + col + 1] = acc[mi][ni][1];
            smf[(m + 8) * U_EPIP + col] = acc[mi][ni][2];
            smf[(m + 8) * U_EPIP + col + 1] = acc[mi][ni][3];
        }
    __syncthreads();

    // demod + bias + noise + leaky in place
    {
        int px = tid & 127;
        int ocl = tid >> 7;
        int my = px >> 4, mx = px & 15;
        int oy = 2 * (y0 + my) + (cls >> 1);
        int ox = 2 * (x0 + mx) + (cls & 1);
        float nz = (*ns1p) * noise1[(n * OH + oy) * OW + ox];
        const float* isgp = g_isg_up + n * CM;
#pragma unroll 4
        for (int ob = 0; ob < 96; ob++) {
            int oc = ob * 2 + ocl;
            float d = smf[px * U_EPIP + oc];
            float val = fmaf(d, isgp[oc], b_up[oc]) + nz;
            val = val > 0.f ? val : 0.2f * val;
            smf[px * U_EPIP + oc] = val;
        }
    }
    __syncthreads();

    // copy smf rows -> g_ht (px-major, 768B per px)
    {
        int px = tid >> 1, part = tid & 1;
        int my = px >> 4, mx = px & 15;
        int oy = 2 * (y0 + my) + (cls >> 1);
        int ox = 2 * (x0 + mx) + (cls & 1);
        uint4* dst = (uint4*)(g_ht + ((size_t)n * 65536 + oy * 256 + ox) * CM);
        const uint4* src = (const uint4*)(smf + px * U_EPIP);
#pragma unroll
        for (int q = 0; q < 24; q++) dst[part * 24 + q] = src[part * 24 + q];
    }
}

// ---------------------------------------------------------------------------
// Conv2 + to-RGB fused, mma.sync implicit GEMM, fully async-staged.
// ---------------------------------------------------------------------------
#define C_ABUF (180 * 208)
#define C_BBUF (128 * 208)
#define C_B0   (3 * C_ABUF)
#define C_CF   (3 * C_ABUF + 3 * C_BBUF)      // 192192
#define C_SMEM (C_CF + 3 * CO * 4)            // 193728
#define EPIP 133

__global__ __launch_bounds__(256, 1) void k_conv2_mma(
    const float* __restrict__ noise2, const float* __restrict__ b_conv,
    const float* __restrict__ ns2p, const float* __restrict__ y,
    const float* __restrict__ w_rgb, const float* __restrict__ b_rgb,
    float* __restrict__ out, float* __restrict__ yout) {
    extern __shared__ __align__(16) char smem[];
    uint32_t sbase = smem_u32(smem);
    float* cf = (float*)(smem + C_CF);

    int tid = threadIdx.x;
    int wid = tid >> 5, lane = tid & 31;
    int wm = wid & 3, wn = wid >> 2;
    int n = blockIdx.z;
    int y0 = blockIdx.y * 8, x0 = blockIdx.x * 16;

    if (tid < CO) {
        float s = g_s_rgb[n * CO + tid];
#pragma unroll
        for (int c = 0; c < 3; c++) cf[c * CO + tid] = w_rgb[c * CO + tid] * s;
    }

    int rowsel = lane & 15, ksel = lane >> 4;

    auto issueA = [&](int cc) {
        const char* asrc = (const char*)g_hs + ((size_t)(n * 6 + cc) * 65536) * 192;
        uint32_t abuf = sbase + (cc % 3) * C_ABUF;
        for (int e = tid; e < 2160; e += 256) {
            int pix = e / 12, q = e % 12;
            int ry = pix / 18, rx = pix % 18;
            int gy = y0 - 1 + ry, gx = x0 - 1 + rx;
            uint32_t ok = ((unsigned)gy < (unsigned)OH && (unsigned)gx < (unsigned)OW)
                              ? 16u : 0u;
            int gyc = gy < 0 ? 0 : (gy > OH - 1 ? OH - 1 : gy);
            int gxc = gx < 0 ? 0 : (gx > OW - 1 ? OW - 1 : gx);
            cpasync16p(abuf + pix * 208 + q * 16,
                       asrc + ((size_t)gyc * 256 + gxc) * 192 + q * 16, ok);
        }
    };
    auto issueB = [&](int it2) {
        const char* bsrc = (const char*)g_wbs + (size_t)it2 * 24576;
        uint32_t bbuf = sbase + C_B0 + (it2 % 3) * C_BBUF;
#pragma unroll
        for (int e = 0; e < 6; e++) {
            int ee = tid + e * 256;
            int row = ee / 12, q = ee % 12;
            cpasync16(bbuf + row * 208 + q * 16, bsrc + row * 192 + q * 16);
        }
    };

    float acc[2][8][4];
#pragma unroll
    for (int mi = 0; mi < 2; mi++)
#pragma unroll
        for (int ni = 0; ni < 8; ni++)
#pragma unroll
            for (int q = 0; q < 4; q++) acc[mi][ni][q] = 0.f;

    issueA(0); CP_COMMIT();
    issueB(0); CP_COMMIT();
    issueA(1); CP_COMMIT();
    issueB(1); CP_COMMIT();

    int c = 0, t = 0;
    for (int it = 0; it < 54; it++) {
        CP_WAIT2();
        __syncthreads();

        if (t == 0 && c + 2 < 6) issueA(c + 2);
        CP_COMMIT();
        if (it + 2 < 54) issueB(it + 2);
        CP_COMMIT();

        uint32_t sA = sbase + (c % 3) * C_ABUF;
        uint32_t sB = sbase + C_B0 + (it % 3) * C_BBUF;
        int ky = t / 3, kx = t % 3;
        int ap0 = ((ky + wm * 2 + 0) * 18 + kx + rowsel) * 208;
        int ap1 = ((ky + wm * 2 + 1) * 18 + kx + rowsel) * 208;
#pragma unroll
        for (int kk = 0; kk < 6; kk++) {
            int koff = (kk * 16 + ksel * 8) * 2;
            uint32_t ar[2][4];
            ldsm_x4(ar[0], sA + ap0 + koff);
            ldsm_x4(ar[1], sA + ap1 + koff);
            uint32_t br[4][4];
#pragma unroll
            for (int nj = 0; nj < 4; nj++)
                ldsm_x4(br[nj], sB + (wn * 64 + nj * 16 + rowsel) * 208 + koff);
#pragma unroll
            for (int mi = 0; mi < 2; mi++)
#pragma unroll
                for (int ni = 0; ni < 8; ni++) {
                    int nj = ni >> 1, pr = ni & 1;
                    mma16816(acc[mi][ni], ar[mi], br[nj][pr], br[nj][pr + 2]);
                }
        }
        __syncthreads();
        if (++t == 9) { t = 0; c++; }
    }

    CP_WAIT0();
    __syncthreads();

    // ---- epilogue: acc -> smf [128 px][128 oc]
    float* smf = (float*)smem;
#pragma unroll
    for (int mi = 0; mi < 2; mi++)
#pragma unroll
        for (int ni = 0; ni < 8; ni++) {
            int m = wm * 32 + mi * 16 + (lane >> 2);
            int col = wn * 64 + ni * 8 + (lane & 3) * 2;
            smf[m * EPIP + col] = acc[mi][ni][0];
            smf[m * EPIP + col + 1] = acc[mi][ni][1];
            smf[(m + 8) * EPIP + col] = acc[mi][ni][2];
            smf[(m + 8) * EPIP + col + 1] = acc[mi][ni][3];
        }
    __syncthreads();

    {
        int px = tid & 127;
        int ocl = tid >> 7;
        int my = px >> 4, mx = px & 15;
        int yy = y0 + my, xx = x0 + mx;
        float nz = (*ns2p) * noise2[(n * OH + yy) * OW + xx];
        const float* isgp = g_isg_cv + n * CO;
#pragma unroll 4
        for (int ob = 0; ob < 64; ob++) {
            int oc = ob * 2 + ocl;
            float d = smf[px * EPIP + oc];
            float val = fmaf(d, isgp[oc], b_conv[oc]) + nz;
            val = val > 0.f ? val : 0.2f * val;
            smf[px * EPIP + oc] = val;
            out[(((size_t)n * CO + oc) * OH + yy) * OW + xx] = val;
        }
    }
    __syncthreads();

    if (tid < 128) {
        int px = tid;
        int my = px >> 4, mx = px & 15;
        int oy = y0 + my, ox = x0 + mx;
        float a0 = b_rgb[0], a1 = b_rgb[1], a2 = b_rgb[2];
        const float* sp = smf + px * EPIP;
#pragma unroll 4
        for (int oc = 0; oc < CO; oc++) {
            float hv = sp[oc];
            a0 = fmaf(hv, cf[oc], a0);
            a1 = fmaf(hv, cf[CO + oc], a1);
            a2 = fmaf(hv, cf[2 * CO + oc], a2);
        }
        a0 = a0 > 0.f ? a0 : 0.2f * a0;
        a1 = a1 > 0.f ? a1 : 0.2f * a1;
        a2 = a2 > 0.f ? a2 : 0.2f * a2;
        float rr[3] = {a0, a1, a2};

        float fy = 0.5f * oy - 0.25f;
        int iyf = (int)floorf(fy);
        float wy = fy - (float)iyf;
        int iy0 = iyf < 0 ? 0 : iyf;
        int iy1 = (iyf + 1) > (HH - 1) ? (HH - 1) : (iyf + 1);
        float fx = 0.5f * ox - 0.25f;
        int ixf = (int)floorf(fx);
        float wx = fx - (float)ixf;
        int ix0 = ixf < 0 ? 0 : ixf;
        int ix1 = (ixf + 1) > (WW - 1) ? (WW - 1) : (ixf + 1);

#pragma unroll
        for (int ch = 0; ch < 3; ch++) {
            const float* yp = y + ((size_t)(n * 3 + ch) * HH) * WW;
            float v00 = yp[iy0 * WW + ix0], v01 = yp[iy0 * WW + ix1];
            float v10 = yp[iy1 * WW + ix0], v11 = yp[iy1 * WW + ix1];
            float vt = v00 + (v01 - v00) * wx;
            float vb = v10 + (v11 - v10) * wx;
            float val = vt + (vb - vt) * wy;
            yout[(((size_t)n * 3 + ch) * OH + oy) * OW + ox] = val + rr[ch];
        }
    }
}

// ---------------------------------------------------------------------------
extern "C" void kernel_launch(void* const* d_in, const int* in_sizes, int n_in,
                              void* d_out, int out_size) {
    const float* x       = (const float*)d_in[0];
    const float* v       = (const float*)d_in[1];
    const float* y       = (const float*)d_in[2];
    const float* noise1  = (const float*)d_in[3];
    const float* noise2  = (const float*)d_in[4];
    const float* w_up    = (const float*)d_in[5];
    const float* b_up    = (const float*)d_in[6];
    const float* sw_up   = (const float*)d_in[7];
    const float* sb_up   = (const float*)d_in[8];
    const float* w_conv  = (const float*)d_in[9];
    const float* b_conv  = (const float*)d_in[10];
    const float* sw_conv = (const float*)d_in[11];
    const float* sb_conv = (const float*)d_in[12];
    const float* w_rgb   = (const float*)d_in[13];
    const float* b_rgb   = (const float*)d_in[14];
    const float* sw_rgb  = (const float*)d_in[15];
    const float* sb_rgb  = (const float*)d_in[16];
    const float* ns1     = (const float*)d_in[17];
    const float* ns2     = (const float*)d_in[18];
    float* out = (float*)d_out;

    (void)in_sizes; (void)n_in; (void)out_size;

    k_prep_w<<<(9 * 8 * CM * 96 + 255) / 256, 256>>>(w_up, w_conv);

    dim3 gst(72, NB);
    k_style_all<<<gst, 256>>>(v, sw_up, sb_up, sw_conv, sb_conv, sw_rgb, sb_rgb);

    dim3 gsg(80, NB);
    k_sigma_all<<<gsg, 128>>>();

    dim3 gxs(128, 8, NB);
    k_xsplit<<<gxs, 256>>>(x);

    cudaFuncSetAttribute(k_upconv_mma, cudaFuncAttributeMaxDynamicSharedMemorySize,
                         U_SMEM);
    dim3 gup(8, 16, NB * 4);
    k_upconv_mma<<<gup, 256, U_SMEM>>>(noise1, b_up, ns1);

    dim3 ghs(4096, 6, NB);
    k_hsplit<<<ghs, 256>>>();

    cudaFuncSetAttribute(k_conv2_mma, cudaFuncAttributeMaxDynamicSharedMemorySize,
                         C_SMEM);
    dim3 gcv(16, 32, NB);
    k_conv2_mma<<<gcv, 256, C_SMEM>>>(noise2, b_conv, ns2, y, w_rgb, b_rgb,
                                      out, out + (size_t)NB * CO * OH * OW);
}